// round 2
// baseline (speedup 1.0000x reference)
#include <cuda_runtime.h>
#include <math.h>

#define Bsz   1024
#define Hsz   512
#define INsz  256
#define OUTsz 256
#define Tsz   128

#define MB 64
#define HB 32
#define KC 32
#define NB 64

// Persistent state (allocation-free scratch)
__device__ float g_h[2][2][Bsz * Hsz];   // [layer][pingpong][B*H]
__device__ float g_c[2][Bsz * Hsz];      // [layer][B*H]
__device__ float g_z[Bsz * INsz];        // current feedback z
__device__ float g_zs[Tsz * Bsz * INsz]; // all z outputs for final linear

__device__ __forceinline__ float sigf(float x) { return 1.f / (1.f + expf(-x)); }

__global__ void init_kernel(const float* __restrict__ z0,
                            const float* __restrict__ h0,
                            const float* __restrict__ c0)
{
    int i = blockIdx.x * blockDim.x + threadIdx.x;
    if (i < Bsz * Hsz) {
        g_h[0][0][i] = h0[i];
        g_h[1][0][i] = h0[Bsz * Hsz + i];
        g_c[0][i]    = c0[i];
        g_c[1][i]    = c0[Bsz * Hsz + i];
    }
    if (i < Bsz * INsz) g_z[i] = z0[i];
}

// Fused LSTM layer: gates = x@Wih^T + h@Whh^T + b, then cell update.
// Block computes a [MB batch x HB hidden] tile across all 4 gates.
__global__ __launch_bounds__(256)
void lstm_layer_kernel(const float* __restrict__ x, int Kx,
                       const float* __restrict__ hprev,
                       float* __restrict__ c,
                       const float* __restrict__ Wih,   // [4H, Kx]
                       const float* __restrict__ Whh,   // [4H, H]
                       const float* __restrict__ bih,
                       const float* __restrict__ bhh,
                       float* __restrict__ hout)
{
    __shared__ float As[KC][MB + 4];        // k-major, padded (float4-aligned rows)
    __shared__ float Ws[4][KC][HB + 2];     // [gate][k][hid], padded (float2-aligned)

    const int tid = threadIdx.x;
    const int tx  = tid & 15;   // hidden dir: 16 threads x 2 units
    const int ty  = tid >> 4;   // batch dir: 16 threads x 4 rows
    const int b0  = blockIdx.x * MB;
    const int h0  = blockIdx.y * HB;

    float acc[4][4][2];  // [batch][gate][hid]
    #pragma unroll
    for (int i = 0; i < 4; i++)
        #pragma unroll
        for (int g = 0; g < 4; g++) { acc[i][g][0] = 0.f; acc[i][g][1] = 0.f; }

    const int nk    = (Kx + Hsz) / KC;
    const int rload = tid >> 3;        // 0..31
    const int kq    = (tid & 7) * 4;   // 0,4,...,28

    for (int kc = 0; kc < nk; kc++) {
        const int k0 = kc * KC;
        const float* ap; int lda; int koff;
        const float* wp; int ldw;
        if (k0 < Kx) { ap = x;     lda = Kx;  koff = k0;      wp = Wih; ldw = Kx;  }
        else         { ap = hprev; lda = Hsz; koff = k0 - Kx; wp = Whh; ldw = Hsz; }

        // Load A tile [MB x KC], store transposed (k-major)
        #pragma unroll
        for (int rr = 0; rr < MB; rr += 32) {
            int r = rload + rr;
            float4 v = *(const float4*)(ap + (size_t)(b0 + r) * lda + koff + kq);
            As[kq + 0][r] = v.x; As[kq + 1][r] = v.y;
            As[kq + 2][r] = v.z; As[kq + 3][r] = v.w;
        }
        // Load W tiles for 4 gates [HB x KC] each, store transposed
        #pragma unroll
        for (int g = 0; g < 4; g++) {
            float4 v = *(const float4*)(wp + (size_t)(g * Hsz + h0 + rload) * ldw + koff + kq);
            Ws[g][kq + 0][rload] = v.x; Ws[g][kq + 1][rload] = v.y;
            Ws[g][kq + 2][rload] = v.z; Ws[g][kq + 3][rload] = v.w;
        }
        __syncthreads();

        #pragma unroll
        for (int kk = 0; kk < KC; kk++) {
            float4 av = *(const float4*)&As[kk][ty * 4];
            float a[4] = {av.x, av.y, av.z, av.w};
            float w[4][2];
            #pragma unroll
            for (int g = 0; g < 4; g++) {
                float2 wv = *(const float2*)&Ws[g][kk][tx * 2];
                w[g][0] = wv.x; w[g][1] = wv.y;
            }
            #pragma unroll
            for (int i = 0; i < 4; i++)
                #pragma unroll
                for (int g = 0; g < 4; g++) {
                    acc[i][g][0] = fmaf(a[i], w[g][0], acc[i][g][0]);
                    acc[i][g][1] = fmaf(a[i], w[g][1], acc[i][g][1]);
                }
        }
        __syncthreads();
    }

    // Fused bias + activations + cell update
    #pragma unroll
    for (int i = 0; i < 4; i++) {
        int b = b0 + ty * 4 + i;
        #pragma unroll
        for (int j = 0; j < 2; j++) {
            int h = h0 + tx * 2 + j;
            float gi = acc[i][0][j] + bih[h]           + bhh[h];
            float gf = acc[i][1][j] + bih[Hsz + h]     + bhh[Hsz + h];
            float gg = acc[i][2][j] + bih[2 * Hsz + h] + bhh[2 * Hsz + h];
            float go = acc[i][3][j] + bih[3 * Hsz + h] + bhh[3 * Hsz + h];
            size_t idx = (size_t)b * Hsz + h;
            float cn = sigf(gf) * c[idx] + sigf(gi) * tanhf(gg);
            c[idx] = cn;
            hout[idx] = sigf(go) * tanhf(cn);
        }
    }
}

// Generic C[M,N] = A[M,K] @ W[N,K]^T + bias ; optional mirror write to C2.
__global__ __launch_bounds__(256)
void linear_kernel(const float* __restrict__ A, int K,
                   const float* __restrict__ W,     // [N, K]
                   const float* __restrict__ bias,
                   float* __restrict__ C, int N,
                   float* __restrict__ C2)
{
    __shared__ float As[KC][MB + 4];
    __shared__ float WsS[KC][NB + 4];

    const int tid = threadIdx.x;
    const int tx  = tid & 15;   // N dir: 16 x 4
    const int ty  = tid >> 4;   // M dir: 16 x 4
    const int b0  = blockIdx.x * MB;
    const int n0  = blockIdx.y * NB;

    float acc[4][4];
    #pragma unroll
    for (int i = 0; i < 4; i++)
        #pragma unroll
        for (int j = 0; j < 4; j++) acc[i][j] = 0.f;

    const int nk    = K / KC;
    const int rload = tid >> 3;
    const int kq    = (tid & 7) * 4;

    for (int kc = 0; kc < nk; kc++) {
        const int k0 = kc * KC;
        #pragma unroll
        for (int rr = 0; rr < MB; rr += 32) {
            int r = rload + rr;
            float4 v = *(const float4*)(A + (size_t)(b0 + r) * K + k0 + kq);
            As[kq + 0][r] = v.x; As[kq + 1][r] = v.y;
            As[kq + 2][r] = v.z; As[kq + 3][r] = v.w;
        }
        #pragma unroll
        for (int rr = 0; rr < NB; rr += 32) {
            int r = rload + rr;
            float4 v = *(const float4*)(W + (size_t)(n0 + r) * K + k0 + kq);
            WsS[kq + 0][r] = v.x; WsS[kq + 1][r] = v.y;
            WsS[kq + 2][r] = v.z; WsS[kq + 3][r] = v.w;
        }
        __syncthreads();

        #pragma unroll
        for (int kk = 0; kk < KC; kk++) {
            float4 av = *(const float4*)&As[kk][ty * 4];
            float4 wv = *(const float4*)&WsS[kk][tx * 4];
            float a[4] = {av.x, av.y, av.z, av.w};
            float w[4] = {wv.x, wv.y, wv.z, wv.w};
            #pragma unroll
            for (int i = 0; i < 4; i++)
                #pragma unroll
                for (int j = 0; j < 4; j++)
                    acc[i][j] = fmaf(a[i], w[j], acc[i][j]);
        }
        __syncthreads();
    }

    #pragma unroll
    for (int i = 0; i < 4; i++) {
        int b = b0 + ty * 4 + i;
        #pragma unroll
        for (int j = 0; j < 4; j++) {
            int n = n0 + tx * 4 + j;
            float v = acc[i][j] + bias[n];
            size_t idx = (size_t)b * N + n;
            C[idx] = v;
            if (C2) C2[idx] = v;
        }
    }
}

extern "C" void kernel_launch(void* const* d_in, const int* in_sizes, int n_in,
                              void* d_out, int out_size)
{
    const float* z0   = (const float*)d_in[0];
    const float* h0   = (const float*)d_in[1];
    const float* c0   = (const float*)d_in[2];
    const float* Wih0 = (const float*)d_in[3];
    const float* Whh0 = (const float*)d_in[4];
    const float* bih0 = (const float*)d_in[5];
    const float* bhh0 = (const float*)d_in[6];
    const float* Wih1 = (const float*)d_in[7];
    const float* Whh1 = (const float*)d_in[8];
    const float* bih1 = (const float*)d_in[9];
    const float* bhh1 = (const float*)d_in[10];
    const float* fcW  = (const float*)d_in[11];
    const float* fcb  = (const float*)d_in[12];
    const float* linW = (const float*)d_in[13];
    const float* linb = (const float*)d_in[14];

    float *hbuf, *cbuf, *zbuf, *zsbuf;
    cudaGetSymbolAddress((void**)&hbuf,  g_h);
    cudaGetSymbolAddress((void**)&cbuf,  g_c);
    cudaGetSymbolAddress((void**)&zbuf,  g_z);
    cudaGetSymbolAddress((void**)&zsbuf, g_zs);

    init_kernel<<<(Bsz * Hsz + 255) / 256, 256>>>(z0, h0, c0);

    const size_t BH = (size_t)Bsz * Hsz;
    dim3 gl(Bsz / MB, Hsz / HB);     // (16,16)
    dim3 gfc(Bsz / MB, INsz / NB);   // (16,4)

    for (int t = 0; t < Tsz; t++) {
        int pr = t & 1, pw = pr ^ 1;
        float* h0r = hbuf + (size_t)(0 * 2 + pr) * BH;
        float* h0w = hbuf + (size_t)(0 * 2 + pw) * BH;
        float* h1r = hbuf + (size_t)(1 * 2 + pr) * BH;
        float* h1w = hbuf + (size_t)(1 * 2 + pw) * BH;

        lstm_layer_kernel<<<gl, 256>>>(zbuf, INsz, h0r, cbuf,      Wih0, Whh0, bih0, bhh0, h0w);
        lstm_layer_kernel<<<gl, 256>>>(h0w,  Hsz,  h1r, cbuf + BH, Wih1, Whh1, bih1, bhh1, h1w);
        linear_kernel<<<gfc, 256>>>(h1w, Hsz, fcW, fcb, zbuf, INsz,
                                    zsbuf + (size_t)t * Bsz * INsz);
    }

    dim3 gfin((Tsz * Bsz) / MB, OUTsz / NB);  // (2048,4)
    linear_kernel<<<gfin, 256>>>(zsbuf, INsz, linW, linb, (float*)d_out, OUTsz, nullptr);
}

// round 4
// speedup vs baseline: 2.3511x; 2.3511x over previous
#include <cuda_runtime.h>
#include <cuda_bf16.h>
#include <math.h>
#include <stdint.h>

typedef __nv_bfloat16 bf16;

#define Bsz   1024
#define Hsz   512
#define INsz  256
#define OUTsz 256
#define Tsz   128
#define K0T   768
#define K1T   1024
#define KFT   512
#define KLT   256

#define LDSW  72                      // smem row stride (elems), 64 data + 8 pad
#define TILEB (128 * LDSW * 2)        // 18432 B per bf16 tile
#define SMEMSZ (1024 + 8 * TILEB)     // 148480 B
#define SMF_STRIDE 132                // fp32 staging row stride

// ---------------- persistent device buffers ----------------
__device__ __align__(256) bf16  g_x0h[2][Bsz * K0T];
__device__ __align__(256) bf16  g_x0l[2][Bsz * K0T];
__device__ __align__(256) bf16  g_x1h[2][Bsz * K1T];
__device__ __align__(256) bf16  g_x1l[2][Bsz * K1T];
__device__ __align__(256) float g_c[2][Bsz * Hsz];
__device__ __align__(256) bf16  g_zsh[Tsz * Bsz * INsz];
__device__ __align__(256) bf16  g_zsl[Tsz * Bsz * INsz];
__device__ __align__(256) bf16  g_W0h[2048 * K0T];
__device__ __align__(256) bf16  g_W0l[2048 * K0T];
__device__ __align__(256) bf16  g_W1h[2048 * K1T];
__device__ __align__(256) bf16  g_W1l[2048 * K1T];
__device__ __align__(256) bf16  g_Wfh[INsz * KFT];
__device__ __align__(256) bf16  g_Wfl[INsz * KFT];
__device__ __align__(256) bf16  g_Wlh[OUTsz * KLT];
__device__ __align__(256) bf16  g_Wll[OUTsz * KLT];
__device__ __align__(256) float g_b0[2048];
__device__ __align__(256) float g_b1[2048];
__device__ __align__(256) float g_bfc[INsz];
__device__ __align__(256) float g_bln[OUTsz];

// ---------------- helpers ----------------
__device__ __forceinline__ uint32_t smem_u32(const void* p) {
    uint32_t a;
    asm("{ .reg .u64 t; cvta.to.shared.u64 t, %1; cvt.u32.u64 %0, t; }" : "=r"(a) : "l"(p));
    return a;
}
__device__ __forceinline__ void cpa16(uint32_t s, const void* g) {
    asm volatile("cp.async.cg.shared.global [%0], [%1], 16;" :: "r"(s), "l"(g));
}
__device__ __forceinline__ void ldsm_x4(uint32_t* r, uint32_t a) {
    asm volatile("ldmatrix.sync.aligned.m8n8.x4.shared.b16 {%0,%1,%2,%3}, [%4];"
                 : "=r"(r[0]), "=r"(r[1]), "=r"(r[2]), "=r"(r[3]) : "r"(a));
}
__device__ __forceinline__ void ldsm_x2(uint32_t* r, uint32_t a) {
    asm volatile("ldmatrix.sync.aligned.m8n8.x2.shared.b16 {%0,%1}, [%2];"
                 : "=r"(r[0]), "=r"(r[1]) : "r"(a));
}
__device__ __forceinline__ void mma16816(float* c, const uint32_t* a, const uint32_t* b) {
    asm volatile(
        "mma.sync.aligned.m16n8k16.row.col.f32.bf16.bf16.f32 "
        "{%0,%1,%2,%3}, {%4,%5,%6,%7}, {%8,%9}, {%0,%1,%2,%3};"
        : "+f"(c[0]), "+f"(c[1]), "+f"(c[2]), "+f"(c[3])
        : "r"(a[0]), "r"(a[1]), "r"(a[2]), "r"(a[3]), "r"(b[0]), "r"(b[1]));
}
__device__ __forceinline__ float sigf(float x) { return 1.f / (1.f + expf(-x)); }
__device__ __forceinline__ void split_bf(float v, bf16& h, bf16& l) {
    h = __float2bfloat16(v);
    l = __float2bfloat16(v - __bfloat162float(h));
}
__device__ __forceinline__ uint32_t pk2(bf16 a, bf16 b) {
    return (uint32_t)__bfloat16_as_ushort(a) | ((uint32_t)__bfloat16_as_ushort(b) << 16);
}

// ---------------- 3-pass bf16 hi/lo GEMM mainloop ----------------
// Computes MTILE x 128 fp32 tile of A @ W^T (split precision) and stages it to
// smem fp32 area at byte offset 1024, stride SMF_STRIDE floats. Block = 256 thr.
template<int MTILE>
__device__ __forceinline__ void gemm_main(
    char* smem,
    const bf16* __restrict__ Ah, const bf16* __restrict__ Al, int lda, int aoff, int m0,
    const bf16* __restrict__ Wh, const bf16* __restrict__ Wl, int ldw, int n0,
    int Ktot)
{
    const uint32_t sb = smem_u32(smem);
    const int tid  = threadIdx.x;
    const int wid  = tid >> 5, lane = tid & 31;
    const int wn   = wid & 3;          // n quadrant (32 cols)
    const int wm   = wid >> 2;         // m half
    const int WMR  = MTILE / 2;
    const int MF   = MTILE / 32;       // m frags per warp

    float acc[MTILE / 32][4][4];
    #pragma unroll
    for (int mi = 0; mi < MF; mi++)
        #pragma unroll
        for (int ni = 0; ni < 4; ni++)
            #pragma unroll
            for (int j = 0; j < 4; j++) acc[mi][ni][j] = 0.f;

    // ldmatrix per-thread offsets (bytes, within a tile)
    const uint32_t a_off = ((wm * WMR + (lane & 15)) * LDSW + (lane >> 4) * 8) * 2;
    const uint32_t b_off = ((wn * 32 + (lane & 7)) * LDSW + ((lane >> 3) & 1) * 8) * 2;

    // cp.async loader coords
    const int lrow = tid >> 3;          // 0..31
    const int lk   = (tid & 7) * 8;     // elem offset (16B granules)

    const int nch = Ktot / 64;

    auto load_chunk = [&](int ch) {
        const uint32_t base = sb + 1024 + (ch & 1) * 4 * TILEB;
        const int k0 = ch * 64;
        #pragma unroll
        for (int i = 0; i < MF; i++) {
            const int r = lrow + i * 32;
            const uint32_t so = base + (r * LDSW + lk) * 2;
            const size_t ga = (size_t)(m0 + r) * lda + aoff + k0 + lk;
            cpa16(so,         Ah + ga);
            cpa16(so + TILEB, Al + ga);
        }
        #pragma unroll
        for (int i = 0; i < 4; i++) {
            const int r = lrow + i * 32;
            const uint32_t so = base + 2 * TILEB + (r * LDSW + lk) * 2;
            const size_t gw = (size_t)(n0 + r) * ldw + k0 + lk;
            cpa16(so,         Wh + gw);
            cpa16(so + TILEB, Wl + gw);
        }
        asm volatile("cp.async.commit_group;");
    };

    load_chunk(0);
    for (int ch = 0; ch < nch; ch++) {
        if (ch + 1 < nch) {
            load_chunk(ch + 1);
            asm volatile("cp.async.wait_group 1;");
        } else {
            asm volatile("cp.async.wait_group 0;");
        }
        __syncthreads();

        const uint32_t base = sb + 1024 + (ch & 1) * 4 * TILEB;
        #pragma unroll
        for (int pass = 0; pass < 3; pass++) {
            const uint32_t ab = base + ((pass == 1) ? TILEB : 0) + a_off;
            const uint32_t bb = base + 2 * TILEB + ((pass == 2) ? TILEB : 0) + b_off;
            #pragma unroll
            for (int ks = 0; ks < 4; ks++) {
                uint32_t B[4][2];
                #pragma unroll
                for (int ni = 0; ni < 4; ni++)
                    ldsm_x2(B[ni], bb + ni * 8 * LDSW * 2 + ks * 32);
                #pragma unroll
                for (int mi = 0; mi < MF; mi++) {
                    uint32_t A4[4];
                    ldsm_x4(A4, ab + mi * 16 * LDSW * 2 + ks * 32);
                    #pragma unroll
                    for (int ni = 0; ni < 4; ni++)
                        mma16816(acc[mi][ni], A4, B[ni]);
                }
            }
        }
        __syncthreads();
    }

    // stage accumulators to fp32 smem
    float* smf = (float*)(smem + 1024);
    #pragma unroll
    for (int mi = 0; mi < MF; mi++) {
        const int m = wm * WMR + mi * 16 + (lane >> 2);
        #pragma unroll
        for (int ni = 0; ni < 4; ni++) {
            const int n = wn * 32 + ni * 8 + (lane & 3) * 2;
            *(float2*)&smf[m * SMF_STRIDE + n]       = make_float2(acc[mi][ni][0], acc[mi][ni][1]);
            *(float2*)&smf[(m + 8) * SMF_STRIDE + n] = make_float2(acc[mi][ni][2], acc[mi][ni][3]);
        }
    }
    __syncthreads();
}

// ---------------- fused LSTM layer ----------------
__global__ void __launch_bounds__(256, 1)
lstm_kernel(const bf16* __restrict__ Ah, const bf16* __restrict__ Al, int lda,
            const bf16* __restrict__ Wh, const bf16* __restrict__ Wl, int Ktot,
            const float* __restrict__ bpk, float* __restrict__ cst,
            bf16* __restrict__ d1h, bf16* __restrict__ d1l, int ld1, int off1,
            bf16* __restrict__ d2h, bf16* __restrict__ d2l, int ld2, int off2)
{
    extern __shared__ char smem[];
    const int tid = threadIdx.x;
    const int m0 = blockIdx.x * 128;
    const int n0 = blockIdx.y * 128;

    if (tid < 128) ((float*)smem)[tid] = bpk[n0 + tid];

    gemm_main<128>(smem, Ah, Al, lda, 0, m0, Wh, Wl, Ktot, n0, Ktot);

    const float* sbias = (const float*)smem;
    const float* smf = (const float*)(smem + 1024);
    const int hb = n0 >> 2;   // 32 hidden units per tile

    #pragma unroll
    for (int it = 0; it < 16; it++) {
        const int idx = it * 256 + tid;
        const int bl = idx >> 5, hl = idx & 31;
        float4 g = *(const float4*)&smf[bl * SMF_STRIDE + hl * 4];
        const float gi = g.x + sbias[hl * 4 + 0];
        const float gf = g.y + sbias[hl * 4 + 1];
        const float gg = g.z + sbias[hl * 4 + 2];
        const float go = g.w + sbias[hl * 4 + 3];
        const size_t ci = (size_t)(m0 + bl) * Hsz + hb + hl;
        const float cc = sigf(gf) * cst[ci] + sigf(gi) * tanhf(gg);
        cst[ci] = cc;
        const float hn = sigf(go) * tanhf(cc);
        bf16 hh, hlw; split_bf(hn, hh, hlw);
        const size_t o1 = (size_t)(m0 + bl) * ld1 + off1 + hb + hl;
        d1h[o1] = hh; d1l[o1] = hlw;
        if (d2h) {
            const size_t o2 = (size_t)(m0 + bl) * ld2 + off2 + hb + hl;
            d2h[o2] = hh; d2l[o2] = hlw;
        }
    }
}

// ---------------- linear (fc / final) ----------------
template<int MTILE>
__global__ void __launch_bounds__(256, 1)
lin_kernel(const bf16* __restrict__ Ah, const bf16* __restrict__ Al, int lda, int aoff,
           const bf16* __restrict__ Wh, const bf16* __restrict__ Wl, int Ktot,
           const float* __restrict__ bias,
           bf16* __restrict__ d1h, bf16* __restrict__ d1l, int ld1, int off1,
           bf16* __restrict__ d2h, bf16* __restrict__ d2l, int ld2,
           float* __restrict__ fout, int ldo)
{
    extern __shared__ char smem[];
    const int tid = threadIdx.x;
    const int m0 = blockIdx.x * MTILE;
    const int n0 = blockIdx.y * 128;

    if (tid < 128) ((float*)smem)[tid] = bias[n0 + tid];

    gemm_main<MTILE>(smem, Ah, Al, lda, aoff, m0, Wh, Wl, Ktot, n0, Ktot);

    const float* sbias = (const float*)smem;
    const float* smf = (const float*)(smem + 1024);

    #pragma unroll
    for (int it = 0; it < MTILE / 8; it++) {
        const int idx = it * 256 + tid;
        const int bl = idx >> 5;
        const int nq = (idx & 31) * 4;
        float4 v = *(const float4*)&smf[bl * SMF_STRIDE + nq];
        v.x += sbias[nq + 0]; v.y += sbias[nq + 1];
        v.z += sbias[nq + 2]; v.w += sbias[nq + 3];
        if (fout)
            *(float4*)&fout[(size_t)(m0 + bl) * ldo + n0 + nq] = v;
        bf16 h0v, l0v, h1v, l1v, h2v, l2v, h3v, l3v;
        split_bf(v.x, h0v, l0v); split_bf(v.y, h1v, l1v);
        split_bf(v.z, h2v, l2v); split_bf(v.w, h3v, l3v);
        const uint2 vh = make_uint2(pk2(h0v, h1v), pk2(h2v, h3v));
        const uint2 vl = make_uint2(pk2(l0v, l1v), pk2(l2v, l3v));
        if (d1h) {
            const size_t o = (size_t)(m0 + bl) * ld1 + off1 + n0 + nq;
            *(uint2*)(d1h + o) = vh; *(uint2*)(d1l + o) = vl;
        }
        if (d2h) {
            const size_t o = (size_t)(m0 + bl) * ld2 + n0 + nq;
            *(uint2*)(d2h + o) = vh; *(uint2*)(d2l + o) = vl;
        }
    }
}

// ---------------- packing / init ----------------
__global__ void pack_lstm(const float* __restrict__ Wih, const float* __restrict__ Whh,
                          const float* __restrict__ bih, const float* __restrict__ bhh,
                          int Kin, bf16* __restrict__ Wph, bf16* __restrict__ Wpl,
                          float* __restrict__ bc)
{
    const int Ktot = Kin + Hsz;
    const size_t total = (size_t)2048 * Ktot;
    for (size_t idx = blockIdx.x * blockDim.x + threadIdx.x; idx < total;
         idx += (size_t)gridDim.x * blockDim.x) {
        int rr = (int)(idx / Ktot);
        int k  = (int)(idx - (size_t)rr * Ktot);
        int h = rr >> 2, g = rr & 3;
        int orow = g * Hsz + h;
        float v = (k < Kin) ? Wih[(size_t)orow * Kin + k]
                            : Whh[(size_t)orow * Hsz + (k - Kin)];
        bf16 hi, lo; split_bf(v, hi, lo);
        Wph[idx] = hi; Wpl[idx] = lo;
    }
    int t = blockIdx.x * blockDim.x + threadIdx.x;
    if (t < 2048) {
        int h = t >> 2, g = t & 3;
        int orow = g * Hsz + h;
        bc[t] = bih[orow] + bhh[orow];
    }
}

__global__ void pack_lin(const float* __restrict__ W, const float* __restrict__ b,
                         int N, int K, bf16* __restrict__ Wph, bf16* __restrict__ Wpl,
                         float* __restrict__ bc)
{
    const size_t total = (size_t)N * K;
    for (size_t idx = blockIdx.x * blockDim.x + threadIdx.x; idx < total;
         idx += (size_t)gridDim.x * blockDim.x) {
        bf16 hi, lo; split_bf(W[idx], hi, lo);
        Wph[idx] = hi; Wpl[idx] = lo;
    }
    int t = blockIdx.x * blockDim.x + threadIdx.x;
    if (t < N) bc[t] = b[t];
}

__global__ void init_state(const float* __restrict__ z0, const float* __restrict__ h0,
                           const float* __restrict__ c0)
{
    const size_t BH = (size_t)Bsz * Hsz;
    for (size_t i = blockIdx.x * blockDim.x + threadIdx.x; i < BH;
         i += (size_t)gridDim.x * blockDim.x) {
        int b = (int)(i >> 9), h = (int)(i & 511);
        bf16 hi, lo;
        split_bf(h0[i], hi, lo);
        g_x0h[0][(size_t)b * K0T + 256 + h] = hi;
        g_x0l[0][(size_t)b * K0T + 256 + h] = lo;
        split_bf(h0[BH + i], hi, lo);
        g_x1h[0][(size_t)b * K1T + 512 + h] = hi;
        g_x1l[0][(size_t)b * K1T + 512 + h] = lo;
        g_c[0][i] = c0[i];
        g_c[1][i] = c0[BH + i];
    }
    const size_t BI = (size_t)Bsz * INsz;
    for (size_t i = blockIdx.x * blockDim.x + threadIdx.x; i < BI;
         i += (size_t)gridDim.x * blockDim.x) {
        int b = (int)(i >> 8), z = (int)(i & 255);
        bf16 hi, lo;
        split_bf(z0[i], hi, lo);
        g_x0h[0][(size_t)b * K0T + z] = hi;
        g_x0l[0][(size_t)b * K0T + z] = lo;
    }
}

// ---------------- host ----------------
extern "C" void kernel_launch(void* const* d_in, const int* in_sizes, int n_in,
                              void* d_out, int out_size)
{
    const float* z0   = (const float*)d_in[0];
    const float* h0   = (const float*)d_in[1];
    const float* c0   = (const float*)d_in[2];
    const float* Wih0 = (const float*)d_in[3];
    const float* Whh0 = (const float*)d_in[4];
    const float* bih0 = (const float*)d_in[5];
    const float* bhh0 = (const float*)d_in[6];
    const float* Wih1 = (const float*)d_in[7];
    const float* Whh1 = (const float*)d_in[8];
    const float* bih1 = (const float*)d_in[9];
    const float* bhh1 = (const float*)d_in[10];
    const float* fcW  = (const float*)d_in[11];
    const float* fcb  = (const float*)d_in[12];
    const float* linW = (const float*)d_in[13];
    const float* linb = (const float*)d_in[14];

    bf16 *x0h, *x0l, *x1h, *x1l, *zsh, *zsl;
    bf16 *W0h, *W0l, *W1h, *W1l, *Wfh, *Wfl, *Wlh, *Wll;
    float *cst, *b0, *b1, *bfc, *bln;
    cudaGetSymbolAddress((void**)&x0h, g_x0h);
    cudaGetSymbolAddress((void**)&x0l, g_x0l);
    cudaGetSymbolAddress((void**)&x1h, g_x1h);
    cudaGetSymbolAddress((void**)&x1l, g_x1l);
    cudaGetSymbolAddress((void**)&zsh, g_zsh);
    cudaGetSymbolAddress((void**)&zsl, g_zsl);
    cudaGetSymbolAddress((void**)&W0h, g_W0h);
    cudaGetSymbolAddress((void**)&W0l, g_W0l);
    cudaGetSymbolAddress((void**)&W1h, g_W1h);
    cudaGetSymbolAddress((void**)&W1l, g_W1l);
    cudaGetSymbolAddress((void**)&Wfh, g_Wfh);
    cudaGetSymbolAddress((void**)&Wfl, g_Wfl);
    cudaGetSymbolAddress((void**)&Wlh, g_Wlh);
    cudaGetSymbolAddress((void**)&Wll, g_Wll);
    cudaGetSymbolAddress((void**)&cst, g_c);
    cudaGetSymbolAddress((void**)&b0,  g_b0);
    cudaGetSymbolAddress((void**)&b1,  g_b1);
    cudaGetSymbolAddress((void**)&bfc, g_bfc);
    cudaGetSymbolAddress((void**)&bln, g_bln);

    cudaFuncSetAttribute(lstm_kernel,     cudaFuncAttributeMaxDynamicSharedMemorySize, SMEMSZ);
    cudaFuncSetAttribute(lin_kernel<64>,  cudaFuncAttributeMaxDynamicSharedMemorySize, SMEMSZ);
    cudaFuncSetAttribute(lin_kernel<128>, cudaFuncAttributeMaxDynamicSharedMemorySize, SMEMSZ);

    pack_lstm<<<2048, 256>>>(Wih0, Whh0, bih0, bhh0, INsz, W0h, W0l, b0);
    pack_lstm<<<2048, 256>>>(Wih1, Whh1, bih1, bhh1, Hsz,  W1h, W1l, b1);
    pack_lin<<<512, 256>>>(fcW,  fcb,  INsz,  KFT, Wfh, Wfl, bfc);
    pack_lin<<<256, 256>>>(linW, linb, OUTsz, KLT, Wlh, Wll, bln);
    init_state<<<2048, 256>>>(z0, h0, c0);

    const size_t X0 = (size_t)Bsz * K0T;
    const size_t X1 = (size_t)Bsz * K1T;
    const size_t BH = (size_t)Bsz * Hsz;

    dim3 gl(Bsz / 128, 2048 / 128);    // (8, 16)
    dim3 gf(Bsz / 64, INsz / 128);     // (16, 2)

    for (int t = 0; t < Tsz; t++) {
        int p = t & 1, pn = p ^ 1;
        // layer 0: x0[p] = (z_t | h0_t) -> h0_new into x1[p][0:512) and x0[pn][256:768)
        lstm_kernel<<<gl, 256, SMEMSZ>>>(
            x0h + p * X0, x0l + p * X0, K0T,
            W0h, W0l, K0T, b0, cst,
            x1h + p * X1, x1l + p * X1, K1T, 0,
            x0h + pn * X0, x0l + pn * X0, K0T, 256);
        // layer 1: x1[p] = (h0_new | h1_t) -> h1_new into x1[pn][512:1024)
        lstm_kernel<<<gl, 256, SMEMSZ>>>(
            x1h + p * X1, x1l + p * X1, K1T,
            W1h, W1l, K1T, b1, cst + BH,
            x1h + pn * X1, x1l + pn * X1, K1T, 512,
            nullptr, nullptr, 0, 0);
        // fc: z_new = h1_new @ fcW^T + fcb -> x0[pn][0:256) and zs[t]
        lin_kernel<64><<<gf, 256, SMEMSZ>>>(
            x1h + pn * X1, x1l + pn * X1, K1T, 512,
            Wfh, Wfl, KFT, bfc,
            x0h + pn * X0, x0l + pn * X0, K0T, 0,
            zsh + (size_t)t * Bsz * INsz, zsl + (size_t)t * Bsz * INsz, INsz,
            nullptr, 0);
    }

    dim3 gfin((Tsz * Bsz) / 128, OUTsz / 128);  // (1024, 2)
    lin_kernel<128><<<gfin, 256, SMEMSZ>>>(
        zsh, zsl, INsz, 0,
        Wlh, Wll, KLT, bln,
        nullptr, nullptr, 0, 0,
        nullptr, nullptr, 0,
        (float*)d_out, OUTsz);
}

// round 5
// speedup vs baseline: 2.4591x; 1.0460x over previous
#include <cuda_runtime.h>
#include <cuda_bf16.h>
#include <math.h>
#include <stdint.h>

typedef __nv_bfloat16 bf16;

#define Bsz   1024
#define Hsz   512
#define INsz  256
#define OUTsz 256
#define Tsz   128
#define K0T   768
#define K1T   1024
#define KFT   512
#define KLT   256

#define LDSW  72                      // smem row stride (elems), 64 data + 8 pad
#define TILEB (128 * LDSW * 2)        // 18432 B per bf16 tile
#define SMEMSZ (1024 + 8 * TILEB)     // 148480 B
#define SMF_STRIDE 132                // fp32 staging row stride

// ---------------- persistent device buffers ----------------
__device__ __align__(256) bf16  g_x0h[2][Bsz * K0T];
__device__ __align__(256) bf16  g_x0l[2][Bsz * K0T];
__device__ __align__(256) bf16  g_x1h[2][Bsz * K1T];
__device__ __align__(256) bf16  g_x1l[2][Bsz * K1T];
__device__ __align__(256) float g_c[2][Bsz * Hsz];
__device__ __align__(256) bf16  g_zsh[Tsz * Bsz * INsz];
__device__ __align__(256) bf16  g_zsl[Tsz * Bsz * INsz];
__device__ __align__(256) bf16  g_W0h[2048 * K0T];
__device__ __align__(256) bf16  g_W0l[2048 * K0T];
__device__ __align__(256) bf16  g_W1h[2048 * K1T];
__device__ __align__(256) bf16  g_W1l[2048 * K1T];
__device__ __align__(256) bf16  g_Wfh[INsz * KFT];
__device__ __align__(256) bf16  g_Wfl[INsz * KFT];
__device__ __align__(256) bf16  g_Wlh[OUTsz * KLT];
__device__ __align__(256) bf16  g_Wll[OUTsz * KLT];
__device__ __align__(256) float g_b0[2048];
__device__ __align__(256) float g_b1[2048];
__device__ __align__(256) float g_bfc[INsz];
__device__ __align__(256) float g_bln[OUTsz];

// ---------------- helpers ----------------
__device__ __forceinline__ uint32_t smem_u32(const void* p) {
    uint32_t a;
    asm("{ .reg .u64 t; cvta.to.shared.u64 t, %1; cvt.u32.u64 %0, t; }" : "=r"(a) : "l"(p));
    return a;
}
__device__ __forceinline__ void cpa16(uint32_t s, const void* g) {
    asm volatile("cp.async.cg.shared.global [%0], [%1], 16;" :: "r"(s), "l"(g));
}
__device__ __forceinline__ void ldsm_x4(uint32_t* r, uint32_t a) {
    asm volatile("ldmatrix.sync.aligned.m8n8.x4.shared.b16 {%0,%1,%2,%3}, [%4];"
                 : "=r"(r[0]), "=r"(r[1]), "=r"(r[2]), "=r"(r[3]) : "r"(a));
}
__device__ __forceinline__ void mma16816(float* c, const uint32_t* a, const uint32_t* b) {
    asm volatile(
        "mma.sync.aligned.m16n8k16.row.col.f32.bf16.bf16.f32 "
        "{%0,%1,%2,%3}, {%4,%5,%6,%7}, {%8,%9}, {%0,%1,%2,%3};"
        : "+f"(c[0]), "+f"(c[1]), "+f"(c[2]), "+f"(c[3])
        : "r"(a[0]), "r"(a[1]), "r"(a[2]), "r"(a[3]), "r"(b[0]), "r"(b[1]));
}
__device__ __forceinline__ float sigf(float x) { return 1.f / (1.f + expf(-x)); }
__device__ __forceinline__ void split_bf(float v, bf16& h, bf16& l) {
    h = __float2bfloat16(v);
    l = __float2bfloat16(v - __bfloat162float(h));
}
__device__ __forceinline__ uint32_t pk2(bf16 a, bf16 b) {
    return (uint32_t)__bfloat16_as_ushort(a) | ((uint32_t)__bfloat16_as_ushort(b) << 16);
}

// ---------------- 3-pass bf16 hi/lo GEMM mainloop (fragment-reuse) ----------------
// Computes MTILE x 128 fp32 tile of A @ W^T (split precision) and stages it to
// smem fp32 area at byte offset 1024, stride SMF_STRIDE floats. Block = 256 thr.
template<int MTILE>
__device__ __forceinline__ void gemm_main(
    char* smem,
    const bf16* __restrict__ Ah, const bf16* __restrict__ Al, int lda, int aoff, int m0,
    const bf16* __restrict__ Wh, const bf16* __restrict__ Wl, int ldw, int n0,
    int Ktot)
{
    const uint32_t sb = smem_u32(smem);
    const int tid  = threadIdx.x;
    const int wid  = tid >> 5, lane = tid & 31;
    const int wn   = wid & 3;          // n quadrant (32 cols)
    const int wm   = wid >> 2;         // m half
    const int WMR  = MTILE / 2;
    const int MF   = MTILE / 32;       // m frags per warp

    float acc[MTILE / 32][4][4];
    #pragma unroll
    for (int mi = 0; mi < MF; mi++)
        #pragma unroll
        for (int ni = 0; ni < 4; ni++)
            #pragma unroll
            for (int j = 0; j < 4; j++) acc[mi][ni][j] = 0.f;

    // ldmatrix per-thread offsets (bytes, within a tile)
    // A x4: lanes 0-15 -> rows m0..15 (k byte 0), lanes 16-31 -> same rows, k byte 16
    const uint32_t a_off = ((wm * WMR + (lane & 15)) * LDSW + (lane >> 4) * 8) * 2;
    // B x4: m=lane>>3: row = +((m>>1)*8) + lane&7 ; kbyte = (m&1)*16
    const uint32_t b_off = ((wn * 32 + ((lane >> 4) << 3) + (lane & 7)) * LDSW
                           + ((lane >> 3) & 1) * 8) * 2;

    // cp.async loader coords
    const int lrow = tid >> 3;          // 0..31
    const int lk   = (tid & 7) * 8;     // elem offset (16B granules)

    const int nch = Ktot / 64;

    auto load_chunk = [&](int ch) {
        const uint32_t base = sb + 1024 + (ch & 1) * 4 * TILEB;
        const int k0 = ch * 64;
        #pragma unroll
        for (int i = 0; i < MF; i++) {
            const int r = lrow + i * 32;
            const uint32_t so = base + (r * LDSW + lk) * 2;
            const size_t ga = (size_t)(m0 + r) * lda + aoff + k0 + lk;
            cpa16(so,         Ah + ga);
            cpa16(so + TILEB, Al + ga);
        }
        #pragma unroll
        for (int i = 0; i < 4; i++) {
            const int r = lrow + i * 32;
            const uint32_t so = base + 2 * TILEB + (r * LDSW + lk) * 2;
            const size_t gw = (size_t)(n0 + r) * ldw + k0 + lk;
            cpa16(so,         Wh + gw);
            cpa16(so + TILEB, Wl + gw);
        }
        asm volatile("cp.async.commit_group;");
    };

    load_chunk(0);
    for (int ch = 0; ch < nch; ch++) {
        if (ch + 1 < nch) {
            load_chunk(ch + 1);
            asm volatile("cp.async.wait_group 1;");
        } else {
            asm volatile("cp.async.wait_group 0;");
        }
        __syncthreads();

        const uint32_t base = sb + 1024 + (ch & 1) * 4 * TILEB;
        const uint32_t abh = base + a_off;
        const uint32_t abl = base + TILEB + a_off;
        const uint32_t bbh = base + 2 * TILEB + b_off;
        const uint32_t bbl = base + 3 * TILEB + b_off;

        #pragma unroll
        for (int ks = 0; ks < 4; ks++) {
            // load all fragments for this k-step once
            uint32_t Ah4[MTILE / 32][4], Al4[MTILE / 32][4];
            uint32_t Bh4[2][4], Bl4[2][4];
            #pragma unroll
            for (int n2 = 0; n2 < 2; n2++) {
                ldsm_x4(Bh4[n2], bbh + n2 * 16 * LDSW * 2 + ks * 32);
                ldsm_x4(Bl4[n2], bbl + n2 * 16 * LDSW * 2 + ks * 32);
            }
            #pragma unroll
            for (int mi = 0; mi < MF; mi++) {
                ldsm_x4(Ah4[mi], abh + mi * 16 * LDSW * 2 + ks * 32);
                ldsm_x4(Al4[mi], abl + mi * 16 * LDSW * 2 + ks * 32);
            }
            // 3 passes from registers: Ah*Wh + Al*Wh + Ah*Wl
            #pragma unroll
            for (int mi = 0; mi < MF; mi++)
                #pragma unroll
                for (int ni = 0; ni < 4; ni++)
                    mma16816(acc[mi][ni], Ah4[mi], &Bh4[ni >> 1][(ni & 1) * 2]);
            #pragma unroll
            for (int mi = 0; mi < MF; mi++)
                #pragma unroll
                for (int ni = 0; ni < 4; ni++)
                    mma16816(acc[mi][ni], Al4[mi], &Bh4[ni >> 1][(ni & 1) * 2]);
            #pragma unroll
            for (int mi = 0; mi < MF; mi++)
                #pragma unroll
                for (int ni = 0; ni < 4; ni++)
                    mma16816(acc[mi][ni], Ah4[mi], &Bl4[ni >> 1][(ni & 1) * 2]);
        }
        __syncthreads();
    }

    // stage accumulators to fp32 smem
    float* smf = (float*)(smem + 1024);
    #pragma unroll
    for (int mi = 0; mi < MF; mi++) {
        const int m = wm * WMR + mi * 16 + (lane >> 2);
        #pragma unroll
        for (int ni = 0; ni < 4; ni++) {
            const int n = wn * 32 + ni * 8 + (lane & 3) * 2;
            *(float2*)&smf[m * SMF_STRIDE + n]       = make_float2(acc[mi][ni][0], acc[mi][ni][1]);
            *(float2*)&smf[(m + 8) * SMF_STRIDE + n] = make_float2(acc[mi][ni][2], acc[mi][ni][3]);
        }
    }
    __syncthreads();
}

// ---------------- fused LSTM layer ----------------
__global__ void __launch_bounds__(256, 1)
lstm_kernel(const bf16* __restrict__ Ah, const bf16* __restrict__ Al, int lda,
            const bf16* __restrict__ Wh, const bf16* __restrict__ Wl, int Ktot,
            const float* __restrict__ bpk, float* __restrict__ cst,
            bf16* __restrict__ d1h, bf16* __restrict__ d1l, int ld1, int off1,
            bf16* __restrict__ d2h, bf16* __restrict__ d2l, int ld2, int off2)
{
    extern __shared__ char smem[];
    const int tid = threadIdx.x;
    const int m0 = blockIdx.x * 128;
    const int n0 = blockIdx.y * 128;

    if (tid < 128) ((float*)smem)[tid] = bpk[n0 + tid];

    gemm_main<128>(smem, Ah, Al, lda, 0, m0, Wh, Wl, Ktot, n0, Ktot);

    const float* sbias = (const float*)smem;
    const float* smf = (const float*)(smem + 1024);
    const int hb = n0 >> 2;   // 32 hidden units per tile

    #pragma unroll
    for (int it = 0; it < 16; it++) {
        const int idx = it * 256 + tid;
        const int bl = idx >> 5, hl = idx & 31;
        float4 g = *(const float4*)&smf[bl * SMF_STRIDE + hl * 4];
        const float gi = g.x + sbias[hl * 4 + 0];
        const float gf = g.y + sbias[hl * 4 + 1];
        const float gg = g.z + sbias[hl * 4 + 2];
        const float go = g.w + sbias[hl * 4 + 3];
        const size_t ci = (size_t)(m0 + bl) * Hsz + hb + hl;
        const float cc = sigf(gf) * cst[ci] + sigf(gi) * tanhf(gg);
        cst[ci] = cc;
        const float hn = sigf(go) * tanhf(cc);
        bf16 hh, hlw; split_bf(hn, hh, hlw);
        const size_t o1 = (size_t)(m0 + bl) * ld1 + off1 + hb + hl;
        d1h[o1] = hh; d1l[o1] = hlw;
        if (d2h) {
            const size_t o2 = (size_t)(m0 + bl) * ld2 + off2 + hb + hl;
            d2h[o2] = hh; d2l[o2] = hlw;
        }
    }
}

// ---------------- linear (fc / final) ----------------
template<int MTILE>
__global__ void __launch_bounds__(256, 1)
lin_kernel(const bf16* __restrict__ Ah, const bf16* __restrict__ Al, int lda, int aoff,
           const bf16* __restrict__ Wh, const bf16* __restrict__ Wl, int Ktot,
           const float* __restrict__ bias,
           bf16* __restrict__ d1h, bf16* __restrict__ d1l, int ld1, int off1,
           bf16* __restrict__ d2h, bf16* __restrict__ d2l, int ld2,
           float* __restrict__ fout, int ldo)
{
    extern __shared__ char smem[];
    const int tid = threadIdx.x;
    const int m0 = blockIdx.x * MTILE;
    const int n0 = blockIdx.y * 128;

    if (tid < 128) ((float*)smem)[tid] = bias[n0 + tid];

    gemm_main<MTILE>(smem, Ah, Al, lda, aoff, m0, Wh, Wl, Ktot, n0, Ktot);

    const float* sbias = (const float*)smem;
    const float* smf = (const float*)(smem + 1024);

    #pragma unroll
    for (int it = 0; it < MTILE / 8; it++) {
        const int idx = it * 256 + tid;
        const int bl = idx >> 5;
        const int nq = (idx & 31) * 4;
        float4 v = *(const float4*)&smf[bl * SMF_STRIDE + nq];
        v.x += sbias[nq + 0]; v.y += sbias[nq + 1];
        v.z += sbias[nq + 2]; v.w += sbias[nq + 3];
        if (fout)
            *(float4*)&fout[(size_t)(m0 + bl) * ldo + n0 + nq] = v;
        bf16 h0v, l0v, h1v, l1v, h2v, l2v, h3v, l3v;
        split_bf(v.x, h0v, l0v); split_bf(v.y, h1v, l1v);
        split_bf(v.z, h2v, l2v); split_bf(v.w, h3v, l3v);
        const uint2 vh = make_uint2(pk2(h0v, h1v), pk2(h2v, h3v));
        const uint2 vl = make_uint2(pk2(l0v, l1v), pk2(l2v, l3v));
        if (d1h) {
            const size_t o = (size_t)(m0 + bl) * ld1 + off1 + n0 + nq;
            *(uint2*)(d1h + o) = vh; *(uint2*)(d1l + o) = vl;
        }
        if (d2h) {
            const size_t o = (size_t)(m0 + bl) * ld2 + n0 + nq;
            *(uint2*)(d2h + o) = vh; *(uint2*)(d2l + o) = vl;
        }
    }
}

// ---------------- single fused prologue (packs + state init) ----------------
__global__ void prologue_kernel(
    const float* __restrict__ z0, const float* __restrict__ h0, const float* __restrict__ c0,
    const float* __restrict__ Wih0, const float* __restrict__ Whh0,
    const float* __restrict__ bih0, const float* __restrict__ bhh0,
    const float* __restrict__ Wih1, const float* __restrict__ Whh1,
    const float* __restrict__ bih1, const float* __restrict__ bhh1,
    const float* __restrict__ fcW, const float* __restrict__ fcb,
    const float* __restrict__ linW, const float* __restrict__ linb)
{
    const size_t stride = (size_t)gridDim.x * blockDim.x;
    const size_t t0 = (size_t)blockIdx.x * blockDim.x + threadIdx.x;

    // pack layer-0 weights (gate-interleaved rows rr = h*4+g)
    for (size_t idx = t0; idx < (size_t)2048 * K0T; idx += stride) {
        int rr = (int)(idx / K0T), k = (int)(idx - (size_t)rr * K0T);
        int h = rr >> 2, g = rr & 3;
        int orow = g * Hsz + h;
        float v = (k < INsz) ? Wih0[(size_t)orow * INsz + k]
                             : Whh0[(size_t)orow * Hsz + (k - INsz)];
        bf16 hi, lo; split_bf(v, hi, lo);
        g_W0h[idx] = hi; g_W0l[idx] = lo;
    }
    // pack layer-1 weights
    for (size_t idx = t0; idx < (size_t)2048 * K1T; idx += stride) {
        int rr = (int)(idx / K1T), k = (int)(idx - (size_t)rr * K1T);
        int h = rr >> 2, g = rr & 3;
        int orow = g * Hsz + h;
        float v = (k < Hsz) ? Wih1[(size_t)orow * Hsz + k]
                            : Whh1[(size_t)orow * Hsz + (k - Hsz)];
        bf16 hi, lo; split_bf(v, hi, lo);
        g_W1h[idx] = hi; g_W1l[idx] = lo;
    }
    // pack fc / lin weights
    for (size_t idx = t0; idx < (size_t)INsz * KFT; idx += stride) {
        bf16 hi, lo; split_bf(fcW[idx], hi, lo);
        g_Wfh[idx] = hi; g_Wfl[idx] = lo;
    }
    for (size_t idx = t0; idx < (size_t)OUTsz * KLT; idx += stride) {
        bf16 hi, lo; split_bf(linW[idx], hi, lo);
        g_Wlh[idx] = hi; g_Wll[idx] = lo;
    }
    // biases
    for (size_t t = t0; t < 2048; t += stride) {
        int h = (int)(t >> 2), g = (int)(t & 3);
        int orow = g * Hsz + h;
        g_b0[t] = bih0[orow] + bhh0[orow];
        g_b1[t] = bih1[orow] + bhh1[orow];
    }
    for (size_t t = t0; t < INsz; t += stride) g_bfc[t] = fcb[t];
    for (size_t t = t0; t < OUTsz; t += stride) g_bln[t] = linb[t];
    // state init
    const size_t BH = (size_t)Bsz * Hsz;
    for (size_t i = t0; i < BH; i += stride) {
        int b = (int)(i >> 9), h = (int)(i & 511);
        bf16 hi, lo;
        split_bf(h0[i], hi, lo);
        g_x0h[0][(size_t)b * K0T + 256 + h] = hi;
        g_x0l[0][(size_t)b * K0T + 256 + h] = lo;
        split_bf(h0[BH + i], hi, lo);
        g_x1h[0][(size_t)b * K1T + 512 + h] = hi;
        g_x1l[0][(size_t)b * K1T + 512 + h] = lo;
        g_c[0][i] = c0[i];
        g_c[1][i] = c0[BH + i];
    }
    for (size_t i = t0; i < (size_t)Bsz * INsz; i += stride) {
        int b = (int)(i >> 8), z = (int)(i & 255);
        bf16 hi, lo;
        split_bf(z0[i], hi, lo);
        g_x0h[0][(size_t)b * K0T + z] = hi;
        g_x0l[0][(size_t)b * K0T + z] = lo;
    }
}

// ---------------- host ----------------
extern "C" void kernel_launch(void* const* d_in, const int* in_sizes, int n_in,
                              void* d_out, int out_size)
{
    const float* z0   = (const float*)d_in[0];
    const float* h0   = (const float*)d_in[1];
    const float* c0   = (const float*)d_in[2];
    const float* Wih0 = (const float*)d_in[3];
    const float* Whh0 = (const float*)d_in[4];
    const float* bih0 = (const float*)d_in[5];
    const float* bhh0 = (const float*)d_in[6];
    const float* Wih1 = (const float*)d_in[7];
    const float* Whh1 = (const float*)d_in[8];
    const float* bih1 = (const float*)d_in[9];
    const float* bhh1 = (const float*)d_in[10];
    const float* fcW  = (const float*)d_in[11];
    const float* fcb  = (const float*)d_in[12];
    const float* linW = (const float*)d_in[13];
    const float* linb = (const float*)d_in[14];

    bf16 *x0h, *x0l, *x1h, *x1l, *zsh, *zsl;
    bf16 *W0h, *W0l, *W1h, *W1l, *Wfh, *Wfl, *Wlh, *Wll;
    float *cst, *b0, *b1, *bfc, *bln;
    cudaGetSymbolAddress((void**)&x0h, g_x0h);
    cudaGetSymbolAddress((void**)&x0l, g_x0l);
    cudaGetSymbolAddress((void**)&x1h, g_x1h);
    cudaGetSymbolAddress((void**)&x1l, g_x1l);
    cudaGetSymbolAddress((void**)&zsh, g_zsh);
    cudaGetSymbolAddress((void**)&zsl, g_zsl);
    cudaGetSymbolAddress((void**)&W0h, g_W0h);
    cudaGetSymbolAddress((void**)&W0l, g_W0l);
    cudaGetSymbolAddress((void**)&W1h, g_W1h);
    cudaGetSymbolAddress((void**)&W1l, g_W1l);
    cudaGetSymbolAddress((void**)&Wfh, g_Wfh);
    cudaGetSymbolAddress((void**)&Wfl, g_Wfl);
    cudaGetSymbolAddress((void**)&Wlh, g_Wlh);
    cudaGetSymbolAddress((void**)&Wll, g_Wll);
    cudaGetSymbolAddress((void**)&cst, g_c);
    cudaGetSymbolAddress((void**)&b0,  g_b0);
    cudaGetSymbolAddress((void**)&b1,  g_b1);
    cudaGetSymbolAddress((void**)&bfc, g_bfc);
    cudaGetSymbolAddress((void**)&bln, g_bln);

    cudaFuncSetAttribute(lstm_kernel,     cudaFuncAttributeMaxDynamicSharedMemorySize, SMEMSZ);
    cudaFuncSetAttribute(lin_kernel<64>,  cudaFuncAttributeMaxDynamicSharedMemorySize, SMEMSZ);
    cudaFuncSetAttribute(lin_kernel<128>, cudaFuncAttributeMaxDynamicSharedMemorySize, SMEMSZ);

    prologue_kernel<<<2048, 256>>>(z0, h0, c0, Wih0, Whh0, bih0, bhh0,
                                   Wih1, Whh1, bih1, bhh1, fcW, fcb, linW, linb);

    const size_t X0 = (size_t)Bsz * K0T;
    const size_t X1 = (size_t)Bsz * K1T;
    const size_t BH = (size_t)Bsz * Hsz;

    dim3 gl(Bsz / 128, 2048 / 128);    // (8, 16)
    dim3 gf(Bsz / 64, INsz / 128);     // (16, 2)

    for (int t = 0; t < Tsz; t++) {
        int p = t & 1, pn = p ^ 1;
        // layer 0: x0[p] = (z_t | h0_t) -> h0_new into x1[p][0:512) and x0[pn][256:768)
        lstm_kernel<<<gl, 256, SMEMSZ>>>(
            x0h + p * X0, x0l + p * X0, K0T,
            W0h, W0l, K0T, b0, cst,
            x1h + p * X1, x1l + p * X1, K1T, 0,
            x0h + pn * X0, x0l + pn * X0, K0T, 256);
        // layer 1: x1[p] = (h0_new | h1_t) -> h1_new into x1[pn][512:1024)
        lstm_kernel<<<gl, 256, SMEMSZ>>>(
            x1h + p * X1, x1l + p * X1, K1T,
            W1h, W1l, K1T, b1, cst + BH,
            x1h + pn * X1, x1l + pn * X1, K1T, 512,
            nullptr, nullptr, 0, 0);
        // fc: z_new = h1_new @ fcW^T + fcb -> x0[pn][0:256) and zs[t]
        lin_kernel<64><<<gf, 256, SMEMSZ>>>(
            x1h + pn * X1, x1l + pn * X1, K1T, 512,
            Wfh, Wfl, KFT, bfc,
            x0h + pn * X0, x0l + pn * X0, K0T, 0,
            zsh + (size_t)t * Bsz * INsz, zsl + (size_t)t * Bsz * INsz, INsz,
            nullptr, 0);
    }

    dim3 gfin((Tsz * Bsz) / 128, OUTsz / 128);  // (1024, 2)
    lin_kernel<128><<<gfin, 256, SMEMSZ>>>(
        zsh, zsl, INsz, 0,
        Wlh, Wll, KLT, bln,
        nullptr, nullptr, 0, 0,
        nullptr, nullptr, 0,
        (float*)d_out, OUTsz);
}

// round 6
// speedup vs baseline: 2.6508x; 1.0779x over previous
#include <cuda_runtime.h>
#include <cuda_bf16.h>
#include <math.h>
#include <stdint.h>

typedef __nv_bfloat16 bf16;

#define Bsz   1024
#define Hsz   512
#define INsz  256
#define OUTsz 256
#define Tsz   128
#define K0T   768
#define K1T   1024
#define KFT   512
#define KLT   256

#define LDSW  72                      // smem row stride (elems), 64 data + 8 pad
#define TILEB (128 * LDSW * 2)        // 18432 B per bf16 tile slot
#define SMEMSZ (1024 + 8 * TILEB)     // 148480 B
#define SMF_STRIDE 132                // fp32 staging row stride
#define NTHR 512

// ---------------- persistent device buffers ----------------
__device__ __align__(256) bf16  g_x0h[2][Bsz * K0T];
__device__ __align__(256) bf16  g_x0l[2][Bsz * K0T];
__device__ __align__(256) bf16  g_x1h[2][Bsz * K1T];
__device__ __align__(256) bf16  g_x1l[2][Bsz * K1T];
__device__ __align__(256) float g_c[2][Bsz * Hsz];
__device__ __align__(256) bf16  g_zsh[Tsz * Bsz * INsz];
__device__ __align__(256) bf16  g_zsl[Tsz * Bsz * INsz];
__device__ __align__(256) bf16  g_W0h[2048 * K0T];
__device__ __align__(256) bf16  g_W0l[2048 * K0T];
__device__ __align__(256) bf16  g_W1h[2048 * K1T];
__device__ __align__(256) bf16  g_W1l[2048 * K1T];
__device__ __align__(256) bf16  g_Wfh[INsz * KFT];
__device__ __align__(256) bf16  g_Wfl[INsz * KFT];
__device__ __align__(256) bf16  g_Wlh[OUTsz * KLT];
__device__ __align__(256) bf16  g_Wll[OUTsz * KLT];
__device__ __align__(256) float g_b0[2048];
__device__ __align__(256) float g_b1[2048];
__device__ __align__(256) float g_bfc[INsz];
__device__ __align__(256) float g_bln[OUTsz];

// ---------------- helpers ----------------
__device__ __forceinline__ uint32_t smem_u32(const void* p) {
    uint32_t a;
    asm("{ .reg .u64 t; cvta.to.shared.u64 t, %1; cvt.u32.u64 %0, t; }" : "=r"(a) : "l"(p));
    return a;
}
__device__ __forceinline__ void cpa16(uint32_t s, const void* g) {
    asm volatile("cp.async.cg.shared.global [%0], [%1], 16;" :: "r"(s), "l"(g));
}
__device__ __forceinline__ void ldsm_x4(uint32_t* r, uint32_t a) {
    asm volatile("ldmatrix.sync.aligned.m8n8.x4.shared.b16 {%0,%1,%2,%3}, [%4];"
                 : "=r"(r[0]), "=r"(r[1]), "=r"(r[2]), "=r"(r[3]) : "r"(a));
}
__device__ __forceinline__ void mma16816(float* c, const uint32_t* a, const uint32_t* b) {
    asm volatile(
        "mma.sync.aligned.m16n8k16.row.col.f32.bf16.bf16.f32 "
        "{%0,%1,%2,%3}, {%4,%5,%6,%7}, {%8,%9}, {%0,%1,%2,%3};"
        : "+f"(c[0]), "+f"(c[1]), "+f"(c[2]), "+f"(c[3])
        : "r"(a[0]), "r"(a[1]), "r"(a[2]), "r"(a[3]), "r"(b[0]), "r"(b[1]));
}
__device__ __forceinline__ float sigf(float x) { return 1.f / (1.f + expf(-x)); }
__device__ __forceinline__ void split_bf(float v, bf16& h, bf16& l) {
    h = __float2bfloat16(v);
    l = __float2bfloat16(v - __bfloat162float(h));
}
__device__ __forceinline__ uint32_t pk2(bf16 a, bf16 b) {
    return (uint32_t)__bfloat16_as_ushort(a) | ((uint32_t)__bfloat16_as_ushort(b) << 16);
}

// ---------------- 3-pass bf16 hi/lo GEMM mainloop ----------------
// 512 threads, 16 warps in 4x4 grid; warp tile (MTILE/4) x (NTILE/4).
// Result staged to fp32 smem at +1024, stride SMF_STRIDE floats.
template<int MTILE, int NTILE>
__device__ __forceinline__ void gemm_main(
    char* smem,
    const bf16* __restrict__ Ah, const bf16* __restrict__ Al, int lda, int aoff, int m0,
    const bf16* __restrict__ Wh, const bf16* __restrict__ Wl, int ldw, int n0,
    int Ktot)
{
    const uint32_t sb = smem_u32(smem);
    const int tid  = threadIdx.x;
    const int wid  = tid >> 5, lane = tid & 31;
    const int wn   = wid & 3;          // n quadrant
    const int wm   = wid >> 2;         // m quadrant
    constexpr int WMR = MTILE / 4;     // rows per warp
    constexpr int WNR = NTILE / 4;     // cols per warp
    constexpr int MF  = WMR / 16;      // 16-row m-frags
    constexpr int NF  = WNR / 8;       // 8-col n-frags
    constexpr int NB2 = NF / 2;        // ldsm.x4 B loads (16 cols each)

    float acc[MF][NF][4];
    #pragma unroll
    for (int mi = 0; mi < MF; mi++)
        #pragma unroll
        for (int ni = 0; ni < NF; ni++)
            #pragma unroll
            for (int j = 0; j < 4; j++) acc[mi][ni][j] = 0.f;

    const uint32_t a_off = ((wm * WMR + (lane & 15)) * LDSW + (lane >> 4) * 8) * 2;
    const uint32_t b_off = ((wn * WNR + ((lane >> 4) << 3) + (lane & 7)) * LDSW
                           + ((lane >> 3) & 1) * 8) * 2;

    // cp.async loader coords (512 threads: 64 rows x 8 granules per sweep)
    const int lrow = tid >> 3;          // 0..63
    const int lk   = (tid & 7) * 8;     // elem offset

    const int nch = Ktot / 64;

    auto load_chunk = [&](int ch) {
        const uint32_t base = sb + 1024 + (ch & 1) * 4 * TILEB;
        const int k0 = ch * 64;
        #pragma unroll
        for (int i = 0; i < MTILE / 64; i++) {
            const int r = lrow + i * 64;
            const uint32_t so = base + (r * LDSW + lk) * 2;
            const size_t ga = (size_t)(m0 + r) * lda + aoff + k0 + lk;
            cpa16(so,         Ah + ga);
            cpa16(so + TILEB, Al + ga);
        }
        #pragma unroll
        for (int i = 0; i < NTILE / 64; i++) {
            const int r = lrow + i * 64;
            const uint32_t so = base + 2 * TILEB + (r * LDSW + lk) * 2;
            const size_t gw = (size_t)(n0 + r) * ldw + k0 + lk;
            cpa16(so,         Wh + gw);
            cpa16(so + TILEB, Wl + gw);
        }
        asm volatile("cp.async.commit_group;");
    };

    load_chunk(0);
    for (int ch = 0; ch < nch; ch++) {
        if (ch + 1 < nch) {
            load_chunk(ch + 1);
            asm volatile("cp.async.wait_group 1;");
        } else {
            asm volatile("cp.async.wait_group 0;");
        }
        __syncthreads();

        const uint32_t base = sb + 1024 + (ch & 1) * 4 * TILEB;
        const uint32_t abh = base + a_off;
        const uint32_t abl = base + TILEB + a_off;
        const uint32_t bbh = base + 2 * TILEB + b_off;
        const uint32_t bbl = base + 3 * TILEB + b_off;

        #pragma unroll
        for (int ks = 0; ks < 4; ks++) {
            uint32_t Ah4[MF][4], Al4[MF][4];
            uint32_t Bh4[NB2][4], Bl4[NB2][4];
            #pragma unroll
            for (int n2 = 0; n2 < NB2; n2++) {
                ldsm_x4(Bh4[n2], bbh + n2 * 16 * LDSW * 2 + ks * 32);
                ldsm_x4(Bl4[n2], bbl + n2 * 16 * LDSW * 2 + ks * 32);
            }
            #pragma unroll
            for (int mi = 0; mi < MF; mi++) {
                ldsm_x4(Ah4[mi], abh + mi * 16 * LDSW * 2 + ks * 32);
                ldsm_x4(Al4[mi], abl + mi * 16 * LDSW * 2 + ks * 32);
            }
            #pragma unroll
            for (int mi = 0; mi < MF; mi++)
                #pragma unroll
                for (int ni = 0; ni < NF; ni++)
                    mma16816(acc[mi][ni], Ah4[mi], &Bh4[ni >> 1][(ni & 1) * 2]);
            #pragma unroll
            for (int mi = 0; mi < MF; mi++)
                #pragma unroll
                for (int ni = 0; ni < NF; ni++)
                    mma16816(acc[mi][ni], Al4[mi], &Bh4[ni >> 1][(ni & 1) * 2]);
            #pragma unroll
            for (int mi = 0; mi < MF; mi++)
                #pragma unroll
                for (int ni = 0; ni < NF; ni++)
                    mma16816(acc[mi][ni], Ah4[mi], &Bl4[ni >> 1][(ni & 1) * 2]);
        }
        __syncthreads();
    }

    // stage accumulators to fp32 smem
    float* smf = (float*)(smem + 1024);
    #pragma unroll
    for (int mi = 0; mi < MF; mi++) {
        const int m = wm * WMR + mi * 16 + (lane >> 2);
        #pragma unroll
        for (int ni = 0; ni < NF; ni++) {
            const int n = wn * WNR + ni * 8 + (lane & 3) * 2;
            *(float2*)&smf[m * SMF_STRIDE + n]       = make_float2(acc[mi][ni][0], acc[mi][ni][1]);
            *(float2*)&smf[(m + 8) * SMF_STRIDE + n] = make_float2(acc[mi][ni][2], acc[mi][ni][3]);
        }
    }
    __syncthreads();
}

// ---------------- fused LSTM layer (128x128 tiles) ----------------
__global__ void __launch_bounds__(NTHR, 1)
lstm_kernel(const bf16* __restrict__ Ah, const bf16* __restrict__ Al, int lda,
            const bf16* __restrict__ Wh, const bf16* __restrict__ Wl, int Ktot,
            const float* __restrict__ bpk, float* __restrict__ cst,
            bf16* __restrict__ d1h, bf16* __restrict__ d1l, int ld1, int off1,
            bf16* __restrict__ d2h, bf16* __restrict__ d2l, int ld2, int off2)
{
    extern __shared__ char smem[];
    const int tid = threadIdx.x;
    const int m0 = blockIdx.x * 128;
    const int n0 = blockIdx.y * 128;

    if (tid < 128) ((float*)smem)[tid] = bpk[n0 + tid];

    gemm_main<128, 128>(smem, Ah, Al, lda, 0, m0, Wh, Wl, Ktot, n0, Ktot);

    const float* sbias = (const float*)smem;
    const float* smf = (const float*)(smem + 1024);
    const int hb = n0 >> 2;   // 32 hidden units per tile

    #pragma unroll
    for (int it = 0; it < 8; it++) {
        const int idx = it * NTHR + tid;        // 0..4095
        const int bl = idx >> 5, hl = idx & 31;
        float4 g = *(const float4*)&smf[bl * SMF_STRIDE + hl * 4];
        const float gi = g.x + sbias[hl * 4 + 0];
        const float gf = g.y + sbias[hl * 4 + 1];
        const float gg = g.z + sbias[hl * 4 + 2];
        const float go = g.w + sbias[hl * 4 + 3];
        const size_t ci = (size_t)(m0 + bl) * Hsz + hb + hl;
        const float cc = sigf(gf) * cst[ci] + sigf(gi) * tanhf(gg);
        cst[ci] = cc;
        const float hn = sigf(go) * tanhf(cc);
        bf16 hh, hlw; split_bf(hn, hh, hlw);
        const size_t o1 = (size_t)(m0 + bl) * ld1 + off1 + hb + hl;
        d1h[o1] = hh; d1l[o1] = hlw;
        if (d2h) {
            const size_t o2 = (size_t)(m0 + bl) * ld2 + off2 + hb + hl;
            d2h[o2] = hh; d2l[o2] = hlw;
        }
    }
}

// ---------------- linear (fc / final) ----------------
template<int MTILE, int NTILE>
__global__ void __launch_bounds__(NTHR, 1)
lin_kernel(const bf16* __restrict__ Ah, const bf16* __restrict__ Al, int lda, int aoff,
           const bf16* __restrict__ Wh, const bf16* __restrict__ Wl, int Ktot,
           const float* __restrict__ bias,
           bf16* __restrict__ d1h, bf16* __restrict__ d1l, int ld1, int off1,
           bf16* __restrict__ d2h, bf16* __restrict__ d2l, int ld2,
           float* __restrict__ fout, int ldo)
{
    extern __shared__ char smem[];
    const int tid = threadIdx.x;
    const int m0 = blockIdx.x * MTILE;
    const int n0 = blockIdx.y * NTILE;

    if (tid < NTILE) ((float*)smem)[tid] = bias[n0 + tid];

    gemm_main<MTILE, NTILE>(smem, Ah, Al, lda, aoff, m0, Wh, Wl, Ktot, n0, Ktot);

    const float* sbias = (const float*)smem;
    const float* smf = (const float*)(smem + 1024);

    constexpr int NQ4 = NTILE / 4;          // float4s per row
    constexpr int TOT = MTILE * NQ4;

    #pragma unroll
    for (int it = 0; it < (TOT + NTHR - 1) / NTHR; it++) {
        const int idx = it * NTHR + tid;
        if (TOT % NTHR != 0 && idx >= TOT) break;
        const int bl = idx / NQ4;
        const int nq = (idx % NQ4) * 4;
        float4 v = *(const float4*)&smf[bl * SMF_STRIDE + nq];
        v.x += sbias[nq + 0]; v.y += sbias[nq + 1];
        v.z += sbias[nq + 2]; v.w += sbias[nq + 3];
        if (fout)
            *(float4*)&fout[(size_t)(m0 + bl) * ldo + n0 + nq] = v;
        bf16 h0v, l0v, h1v, l1v, h2v, l2v, h3v, l3v;
        split_bf(v.x, h0v, l0v); split_bf(v.y, h1v, l1v);
        split_bf(v.z, h2v, l2v); split_bf(v.w, h3v, l3v);
        const uint2 vh = make_uint2(pk2(h0v, h1v), pk2(h2v, h3v));
        const uint2 vl = make_uint2(pk2(l0v, l1v), pk2(l2v, l3v));
        if (d1h) {
            const size_t o = (size_t)(m0 + bl) * ld1 + off1 + n0 + nq;
            *(uint2*)(d1h + o) = vh; *(uint2*)(d1l + o) = vl;
        }
        if (d2h) {
            const size_t o = (size_t)(m0 + bl) * ld2 + n0 + nq;
            *(uint2*)(d2h + o) = vh; *(uint2*)(d2l + o) = vl;
        }
    }
}

// ---------------- single fused prologue (packs + state init) ----------------
__global__ void prologue_kernel(
    const float* __restrict__ z0, const float* __restrict__ h0, const float* __restrict__ c0,
    const float* __restrict__ Wih0, const float* __restrict__ Whh0,
    const float* __restrict__ bih0, const float* __restrict__ bhh0,
    const float* __restrict__ Wih1, const float* __restrict__ Whh1,
    const float* __restrict__ bih1, const float* __restrict__ bhh1,
    const float* __restrict__ fcW, const float* __restrict__ fcb,
    const float* __restrict__ linW, const float* __restrict__ linb)
{
    const size_t stride = (size_t)gridDim.x * blockDim.x;
    const size_t t0 = (size_t)blockIdx.x * blockDim.x + threadIdx.x;

    for (size_t idx = t0; idx < (size_t)2048 * K0T; idx += stride) {
        int rr = (int)(idx / K0T), k = (int)(idx - (size_t)rr * K0T);
        int h = rr >> 2, g = rr & 3;
        int orow = g * Hsz + h;
        float v = (k < INsz) ? Wih0[(size_t)orow * INsz + k]
                             : Whh0[(size_t)orow * Hsz + (k - INsz)];
        bf16 hi, lo; split_bf(v, hi, lo);
        g_W0h[idx] = hi; g_W0l[idx] = lo;
    }
    for (size_t idx = t0; idx < (size_t)2048 * K1T; idx += stride) {
        int rr = (int)(idx / K1T), k = (int)(idx - (size_t)rr * K1T);
        int h = rr >> 2, g = rr & 3;
        int orow = g * Hsz + h;
        float v = (k < Hsz) ? Wih1[(size_t)orow * Hsz + k]
                            : Whh1[(size_t)orow * Hsz + (k - Hsz)];
        bf16 hi, lo; split_bf(v, hi, lo);
        g_W1h[idx] = hi; g_W1l[idx] = lo;
    }
    for (size_t idx = t0; idx < (size_t)INsz * KFT; idx += stride) {
        bf16 hi, lo; split_bf(fcW[idx], hi, lo);
        g_Wfh[idx] = hi; g_Wfl[idx] = lo;
    }
    for (size_t idx = t0; idx < (size_t)OUTsz * KLT; idx += stride) {
        bf16 hi, lo; split_bf(linW[idx], hi, lo);
        g_Wlh[idx] = hi; g_Wll[idx] = lo;
    }
    for (size_t t = t0; t < 2048; t += stride) {
        int h = (int)(t >> 2), g = (int)(t & 3);
        int orow = g * Hsz + h;
        g_b0[t] = bih0[orow] + bhh0[orow];
        g_b1[t] = bih1[orow] + bhh1[orow];
    }
    for (size_t t = t0; t < INsz; t += stride) g_bfc[t] = fcb[t];
    for (size_t t = t0; t < OUTsz; t += stride) g_bln[t] = linb[t];
    const size_t BH = (size_t)Bsz * Hsz;
    for (size_t i = t0; i < BH; i += stride) {
        int b = (int)(i >> 9), h = (int)(i & 511);
        bf16 hi, lo;
        split_bf(h0[i], hi, lo);
        g_x0h[0][(size_t)b * K0T + 256 + h] = hi;
        g_x0l[0][(size_t)b * K0T + 256 + h] = lo;
        split_bf(h0[BH + i], hi, lo);
        g_x1h[0][(size_t)b * K1T + 512 + h] = hi;
        g_x1l[0][(size_t)b * K1T + 512 + h] = lo;
        g_c[0][i] = c0[i];
        g_c[1][i] = c0[BH + i];
    }
    for (size_t i = t0; i < (size_t)Bsz * INsz; i += stride) {
        int b = (int)(i >> 8), z = (int)(i & 255);
        bf16 hi, lo;
        split_bf(z0[i], hi, lo);
        g_x0h[0][(size_t)b * K0T + z] = hi;
        g_x0l[0][(size_t)b * K0T + z] = lo;
    }
}

// ---------------- host ----------------
extern "C" void kernel_launch(void* const* d_in, const int* in_sizes, int n_in,
                              void* d_out, int out_size)
{
    const float* z0   = (const float*)d_in[0];
    const float* h0   = (const float*)d_in[1];
    const float* c0   = (const float*)d_in[2];
    const float* Wih0 = (const float*)d_in[3];
    const float* Whh0 = (const float*)d_in[4];
    const float* bih0 = (const float*)d_in[5];
    const float* bhh0 = (const float*)d_in[6];
    const float* Wih1 = (const float*)d_in[7];
    const float* Whh1 = (const float*)d_in[8];
    const float* bih1 = (const float*)d_in[9];
    const float* bhh1 = (const float*)d_in[10];
    const float* fcW  = (const float*)d_in[11];
    const float* fcb  = (const float*)d_in[12];
    const float* linW = (const float*)d_in[13];
    const float* linb = (const float*)d_in[14];

    bf16 *x0h, *x0l, *x1h, *x1l, *zsh, *zsl;
    bf16 *W0h, *W0l, *W1h, *W1l, *Wfh, *Wfl, *Wlh, *Wll;
    float *cst, *b0, *b1, *bfc, *bln;
    cudaGetSymbolAddress((void**)&x0h, g_x0h);
    cudaGetSymbolAddress((void**)&x0l, g_x0l);
    cudaGetSymbolAddress((void**)&x1h, g_x1h);
    cudaGetSymbolAddress((void**)&x1l, g_x1l);
    cudaGetSymbolAddress((void**)&zsh, g_zsh);
    cudaGetSymbolAddress((void**)&zsl, g_zsl);
    cudaGetSymbolAddress((void**)&W0h, g_W0h);
    cudaGetSymbolAddress((void**)&W0l, g_W0l);
    cudaGetSymbolAddress((void**)&W1h, g_W1h);
    cudaGetSymbolAddress((void**)&W1l, g_W1l);
    cudaGetSymbolAddress((void**)&Wfh, g_Wfh);
    cudaGetSymbolAddress((void**)&Wfl, g_Wfl);
    cudaGetSymbolAddress((void**)&Wlh, g_Wlh);
    cudaGetSymbolAddress((void**)&Wll, g_Wll);
    cudaGetSymbolAddress((void**)&cst, g_c);
    cudaGetSymbolAddress((void**)&b0,  g_b0);
    cudaGetSymbolAddress((void**)&b1,  g_b1);
    cudaGetSymbolAddress((void**)&bfc, g_bfc);
    cudaGetSymbolAddress((void**)&bln, g_bln);

    cudaFuncSetAttribute(lstm_kernel, cudaFuncAttributeMaxDynamicSharedMemorySize, SMEMSZ);
    cudaFuncSetAttribute((const void*)lin_kernel<64, 64>,
                         cudaFuncAttributeMaxDynamicSharedMemorySize, SMEMSZ);
    cudaFuncSetAttribute((const void*)lin_kernel<128, 128>,
                         cudaFuncAttributeMaxDynamicSharedMemorySize, SMEMSZ);

    prologue_kernel<<<2048, 256>>>(z0, h0, c0, Wih0, Whh0, bih0, bhh0,
                                   Wih1, Whh1, bih1, bhh1, fcW, fcb, linW, linb);

    const size_t X0 = (size_t)Bsz * K0T;
    const size_t X1 = (size_t)Bsz * K1T;
    const size_t BH = (size_t)Bsz * Hsz;

    dim3 gl(Bsz / 128, 2048 / 128);    // (8, 16) = 128 CTAs
    dim3 gf(Bsz / 64, INsz / 64);      // (16, 4) = 64 CTAs

    for (int t = 0; t < Tsz; t++) {
        int p = t & 1, pn = p ^ 1;
        // layer 0: x0[p] = (z_t | h0_t) -> h0_new into x1[p][0:512) and x0[pn][256:768)
        lstm_kernel<<<gl, NTHR, SMEMSZ>>>(
            x0h + p * X0, x0l + p * X0, K0T,
            W0h, W0l, K0T, b0, cst,
            x1h + p * X1, x1l + p * X1, K1T, 0,
            x0h + pn * X0, x0l + pn * X0, K0T, 256);
        // layer 1: x1[p] = (h0_new | h1_t) -> h1_new into x1[pn][512:1024)
        lstm_kernel<<<gl, NTHR, SMEMSZ>>>(
            x1h + p * X1, x1l + p * X1, K1T,
            W1h, W1l, K1T, b1, cst + BH,
            x1h + pn * X1, x1l + pn * X1, K1T, 512,
            nullptr, nullptr, 0, 0);
        // fc: z_new = h1_new @ fcW^T + fcb -> x0[pn][0:256) and zs[t]
        lin_kernel<64, 64><<<gf, NTHR, SMEMSZ>>>(
            x1h + pn * X1, x1l + pn * X1, K1T, 512,
            Wfh, Wfl, KFT, bfc,
            x0h + pn * X0, x0l + pn * X0, K0T, 0,
            zsh + (size_t)t * Bsz * INsz, zsl + (size_t)t * Bsz * INsz, INsz,
            nullptr, 0);
    }

    dim3 gfin((Tsz * Bsz) / 128, OUTsz / 128);  // (1024, 2)
    lin_kernel<128, 128><<<gfin, NTHR, SMEMSZ>>>(
        zsh, zsl, INsz, 0,
        Wlh, Wll, KLT, bln,
        nullptr, nullptr, 0, 0,
        nullptr, nullptr, 0,
        (float*)d_out, OUTsz);
}

// round 8
// speedup vs baseline: 2.7107x; 1.0226x over previous
#include <cuda_runtime.h>
#include <cuda_bf16.h>
#include <math.h>
#include <stdint.h>

typedef __nv_bfloat16 bf16;

#define Bsz   1024
#define Hsz   512
#define INsz  256
#define OUTsz 256
#define Tsz   128
#define K0T   768
#define K1T   1024
#define KFT   512
#define KLT   256

#define LDSW  72                      // smem row stride (elems), 64 data + 8 pad
#define TILEB (128 * LDSW * 2)        // 18432 B per bf16 tile slot
#define SMEMSZ (1024 + 8 * TILEB)     // 148480 B
#define SMF_STRIDE 132                // fp32 staging row stride
#define NTHR 512
#define GRIDC 128

// ---------------- persistent device buffers ----------------
__device__ __align__(256) bf16  g_x0h[2][Bsz * K0T];
__device__ __align__(256) bf16  g_x0l[2][Bsz * K0T];
__device__ __align__(256) bf16  g_x1h[2][Bsz * K1T];
__device__ __align__(256) bf16  g_x1l[2][Bsz * K1T];
__device__ __align__(256) float g_c[2][Bsz * Hsz];
__device__ __align__(256) bf16  g_zsh[Tsz * Bsz * INsz];
__device__ __align__(256) bf16  g_zsl[Tsz * Bsz * INsz];
__device__ __align__(256) bf16  g_W0h[2048 * K0T];
__device__ __align__(256) bf16  g_W0l[2048 * K0T];
__device__ __align__(256) bf16  g_W1h[2048 * K1T];
__device__ __align__(256) bf16  g_W1l[2048 * K1T];
__device__ __align__(256) bf16  g_Wfh[INsz * KFT];
__device__ __align__(256) bf16  g_Wfl[INsz * KFT];
__device__ __align__(256) bf16  g_Wlh[OUTsz * KLT];
__device__ __align__(256) bf16  g_Wll[OUTsz * KLT];
__device__ __align__(256) float g_b0[2048];
__device__ __align__(256) float g_b1[2048];
__device__ __align__(256) float g_bfc[INsz];
__device__ __align__(256) float g_bln[OUTsz];
__device__ unsigned g_count;          // grid barrier counter (reset each launch)

// ---------------- helpers ----------------
__device__ __forceinline__ uint32_t smem_u32(const void* p) {
    uint32_t a;
    asm("{ .reg .u64 t; cvta.to.shared.u64 t, %1; cvt.u32.u64 %0, t; }" : "=r"(a) : "l"(p));
    return a;
}
__device__ __forceinline__ void cpa16(uint32_t s, const void* g) {
    asm volatile("cp.async.cg.shared.global [%0], [%1], 16;" :: "r"(s), "l"(g));
}
__device__ __forceinline__ void ldsm_x4(uint32_t* r, uint32_t a) {
    asm volatile("ldmatrix.sync.aligned.m8n8.x4.shared.b16 {%0,%1,%2,%3}, [%4];"
                 : "=r"(r[0]), "=r"(r[1]), "=r"(r[2]), "=r"(r[3]) : "r"(a));
}
__device__ __forceinline__ void mma16816(float* c, const uint32_t* a, const uint32_t* b) {
    asm volatile(
        "mma.sync.aligned.m16n8k16.row.col.f32.bf16.bf16.f32 "
        "{%0,%1,%2,%3}, {%4,%5,%6,%7}, {%8,%9}, {%0,%1,%2,%3};"
        : "+f"(c[0]), "+f"(c[1]), "+f"(c[2]), "+f"(c[3])
        : "r"(a[0]), "r"(a[1]), "r"(a[2]), "r"(a[3]), "r"(b[0]), "r"(b[1]));
}
__device__ __forceinline__ float sigf(float x) { return 1.f / (1.f + expf(-x)); }
__device__ __forceinline__ void split_bf(float v, bf16& h, bf16& l) {
    h = __float2bfloat16(v);
    l = __float2bfloat16(v - __bfloat162float(h));
}
__device__ __forceinline__ uint32_t pk2(bf16 a, bf16 b) {
    return (uint32_t)__bfloat16_as_ushort(a) | ((uint32_t)__bfloat16_as_ushort(b) << 16);
}

// Software grid barrier. All cross-CTA data moves through cp.async.cg (L2-only),
// so __threadfence + counter is sufficient for coherence.
__device__ __forceinline__ void gridbar(unsigned target) {
    __threadfence();
    __syncthreads();
    if (threadIdx.x == 0) {
        atomicAdd(&g_count, 1u);
        while (((volatile unsigned*)&g_count)[0] < target) __nanosleep(64);
    }
    __syncthreads();
}

// ---------------- 3-pass bf16 hi/lo GEMM mainloop ----------------
// 512 threads, 16 warps in 4x4 grid; warp tile (MTILE/4) x (NTILE/4).
// Result staged to fp32 smem at +1024, stride SMF_STRIDE floats.
template<int MTILE, int NTILE>
__device__ __forceinline__ void gemm_main(
    char* smem,
    const bf16* __restrict__ Ah, const bf16* __restrict__ Al, int lda, int aoff, int m0,
    const bf16* __restrict__ Wh, const bf16* __restrict__ Wl, int ldw, int n0,
    int Ktot)
{
    const uint32_t sb = smem_u32(smem);
    const int tid  = threadIdx.x;
    const int wid  = tid >> 5, lane = tid & 31;
    const int wn   = wid & 3;          // n quadrant
    const int wm   = wid >> 2;         // m quadrant
    constexpr int WMR = MTILE / 4;     // rows per warp
    constexpr int WNR = NTILE / 4;     // cols per warp
    constexpr int MF  = WMR / 16;      // 16-row m-frags
    constexpr int NF  = WNR / 8;       // 8-col n-frags
    constexpr int NB2 = NF / 2;        // ldsm.x4 B loads (16 cols each)

    float acc[MF][NF][4];
    #pragma unroll
    for (int mi = 0; mi < MF; mi++)
        #pragma unroll
        for (int ni = 0; ni < NF; ni++)
            #pragma unroll
            for (int j = 0; j < 4; j++) acc[mi][ni][j] = 0.f;

    const uint32_t a_off = ((wm * WMR + (lane & 15)) * LDSW + (lane >> 4) * 8) * 2;
    const uint32_t b_off = ((wn * WNR + ((lane >> 4) << 3) + (lane & 7)) * LDSW
                           + ((lane >> 3) & 1) * 8) * 2;

    const int lrow = tid >> 3;          // 0..63
    const int lk   = (tid & 7) * 8;     // elem offset

    const int nch = Ktot / 64;

    auto load_chunk = [&](int ch) {
        const uint32_t base = sb + 1024 + (ch & 1) * 4 * TILEB;
        const int k0 = ch * 64;
        #pragma unroll
        for (int i = 0; i < MTILE / 64; i++) {
            const int r = lrow + i * 64;
            const uint32_t so = base + (r * LDSW + lk) * 2;
            const size_t ga = (size_t)(m0 + r) * lda + aoff + k0 + lk;
            cpa16(so,         Ah + ga);
            cpa16(so + TILEB, Al + ga);
        }
        #pragma unroll
        for (int i = 0; i < NTILE / 64; i++) {
            const int r = lrow + i * 64;
            const uint32_t so = base + 2 * TILEB + (r * LDSW + lk) * 2;
            const size_t gw = (size_t)(n0 + r) * ldw + k0 + lk;
            cpa16(so,         Wh + gw);
            cpa16(so + TILEB, Wl + gw);
        }
        asm volatile("cp.async.commit_group;");
    };

    load_chunk(0);
    for (int ch = 0; ch < nch; ch++) {
        if (ch + 1 < nch) {
            load_chunk(ch + 1);
            asm volatile("cp.async.wait_group 1;");
        } else {
            asm volatile("cp.async.wait_group 0;");
        }
        __syncthreads();

        const uint32_t base = sb + 1024 + (ch & 1) * 4 * TILEB;
        const uint32_t abh = base + a_off;
        const uint32_t abl = base + TILEB + a_off;
        const uint32_t bbh = base + 2 * TILEB + b_off;
        const uint32_t bbl = base + 3 * TILEB + b_off;

        #pragma unroll
        for (int ks = 0; ks < 4; ks++) {
            uint32_t Ah4[MF][4], Al4[MF][4];
            uint32_t Bh4[NB2][4], Bl4[NB2][4];
            #pragma unroll
            for (int n2 = 0; n2 < NB2; n2++) {
                ldsm_x4(Bh4[n2], bbh + n2 * 16 * LDSW * 2 + ks * 32);
                ldsm_x4(Bl4[n2], bbl + n2 * 16 * LDSW * 2 + ks * 32);
            }
            #pragma unroll
            for (int mi = 0; mi < MF; mi++) {
                ldsm_x4(Ah4[mi], abh + mi * 16 * LDSW * 2 + ks * 32);
                ldsm_x4(Al4[mi], abl + mi * 16 * LDSW * 2 + ks * 32);
            }
            #pragma unroll
            for (int mi = 0; mi < MF; mi++)
                #pragma unroll
                for (int ni = 0; ni < NF; ni++)
                    mma16816(acc[mi][ni], Ah4[mi], &Bh4[ni >> 1][(ni & 1) * 2]);
            #pragma unroll
            for (int mi = 0; mi < MF; mi++)
                #pragma unroll
                for (int ni = 0; ni < NF; ni++)
                    mma16816(acc[mi][ni], Al4[mi], &Bh4[ni >> 1][(ni & 1) * 2]);
            #pragma unroll
            for (int mi = 0; mi < MF; mi++)
                #pragma unroll
                for (int ni = 0; ni < NF; ni++)
                    mma16816(acc[mi][ni], Ah4[mi], &Bl4[ni >> 1][(ni & 1) * 2]);
        }
        __syncthreads();
    }

    // stage accumulators to fp32 smem
    float* smf = (float*)(smem + 1024);
    #pragma unroll
    for (int mi = 0; mi < MF; mi++) {
        const int m = wm * WMR + mi * 16 + (lane >> 2);
        #pragma unroll
        for (int ni = 0; ni < NF; ni++) {
            const int n = wn * WNR + ni * 8 + (lane & 3) * 2;
            *(float2*)&smf[m * SMF_STRIDE + n]       = make_float2(acc[mi][ni][0], acc[mi][ni][1]);
            *(float2*)&smf[(m + 8) * SMF_STRIDE + n] = make_float2(acc[mi][ni][2], acc[mi][ni][3]);
        }
    }
    __syncthreads();
}

// ---------------- LSTM epilogue (128x128 tile) ----------------
__device__ __forceinline__ void lstm_epilogue(
    char* smem, int m0, int n0, float* __restrict__ cst,
    bf16* __restrict__ d1h, bf16* __restrict__ d1l, int ld1, int off1,
    bf16* __restrict__ d2h, bf16* __restrict__ d2l, int ld2, int off2)
{
    const int tid = threadIdx.x;
    const float* sbias = (const float*)smem;
    const float* smf = (const float*)(smem + 1024);
    const int hb = n0 >> 2;

    #pragma unroll
    for (int it = 0; it < 8; it++) {
        const int idx = it * NTHR + tid;
        const int bl = idx >> 5, hl = idx & 31;
        float4 g = *(const float4*)&smf[bl * SMF_STRIDE + hl * 4];
        const float gi = g.x + sbias[hl * 4 + 0];
        const float gf = g.y + sbias[hl * 4 + 1];
        const float gg = g.z + sbias[hl * 4 + 2];
        const float go = g.w + sbias[hl * 4 + 3];
        const size_t ci = (size_t)(m0 + bl) * Hsz + hb + hl;
        const float cc = sigf(gf) * cst[ci] + sigf(gi) * tanhf(gg);
        cst[ci] = cc;
        const float hn = sigf(go) * tanhf(cc);
        bf16 hh, hlw; split_bf(hn, hh, hlw);
        const size_t o1 = (size_t)(m0 + bl) * ld1 + off1 + hb + hl;
        d1h[o1] = hh; d1l[o1] = hlw;
        if (d2h) {
            const size_t o2 = (size_t)(m0 + bl) * ld2 + off2 + hb + hl;
            d2h[o2] = hh; d2l[o2] = hlw;
        }
    }
}

// ---------------- FC epilogue (64x64 tile) ----------------
__device__ __forceinline__ void fc_epilogue64(
    char* smem, int m0, int n0,
    bf16* __restrict__ d1h, bf16* __restrict__ d1l, int ld1,
    bf16* __restrict__ zsh, bf16* __restrict__ zsl)
{
    const int tid = threadIdx.x;
    const float* sbias = (const float*)smem;
    const float* smf = (const float*)(smem + 1024);

    #pragma unroll
    for (int it = 0; it < 2; it++) {
        const int idx = it * NTHR + tid;   // 0..1023
        const int bl = idx >> 4;
        const int nq = (idx & 15) * 4;
        float4 v = *(const float4*)&smf[bl * SMF_STRIDE + nq];
        v.x += sbias[nq + 0]; v.y += sbias[nq + 1];
        v.z += sbias[nq + 2]; v.w += sbias[nq + 3];
        bf16 h0v, l0v, h1v, l1v, h2v, l2v, h3v, l3v;
        split_bf(v.x, h0v, l0v); split_bf(v.y, h1v, l1v);
        split_bf(v.z, h2v, l2v); split_bf(v.w, h3v, l3v);
        const uint2 vh = make_uint2(pk2(h0v, h1v), pk2(h2v, h3v));
        const uint2 vl = make_uint2(pk2(l0v, l1v), pk2(l2v, l3v));
        const size_t o1 = (size_t)(m0 + bl) * ld1 + n0 + nq;
        *(uint2*)(d1h + o1) = vh; *(uint2*)(d1l + o1) = vl;
        const size_t o2 = (size_t)(m0 + bl) * INsz + n0 + nq;
        *(uint2*)(zsh + o2) = vh; *(uint2*)(zsl + o2) = vl;
    }
}

// ---------------- persistent decoder: all 128 steps in one kernel ----------------
__global__ void __launch_bounds__(NTHR, 1) decoder_persistent()
{
    extern __shared__ char smem[];
    const int cta = blockIdx.x;
    const int tid = threadIdx.x;
    unsigned gen = 0;

    for (int t = 0; t < Tsz; t++) {
        const int p = t & 1, pn = p ^ 1;

        // ---- layer 0: (z_t | h0_t) -> h0_new into x1[p][0:512) and x0[pn][256:768)
        {
            const int m0 = (cta & 7) * 128, n0 = (cta >> 3) * 128;
            if (tid < 128) ((float*)smem)[tid] = g_b0[n0 + tid];
            gemm_main<128, 128>(smem, g_x0h[p], g_x0l[p], K0T, 0, m0,
                                g_W0h, g_W0l, K0T, n0, K0T);
            lstm_epilogue(smem, m0, n0, g_c[0],
                          g_x1h[p], g_x1l[p], K1T, 0,
                          g_x0h[pn], g_x0l[pn], K0T, 256);
        }
        gridbar(++gen * GRIDC);

        // ---- layer 1: (h0_new | h1_t) -> h1_new into x1[pn][512:1024)
        {
            const int m0 = (cta & 7) * 128, n0 = (cta >> 3) * 128;
            if (tid < 128) ((float*)smem)[tid] = g_b1[n0 + tid];
            gemm_main<128, 128>(smem, g_x1h[p], g_x1l[p], K1T, 0, m0,
                                g_W1h, g_W1l, K1T, n0, K1T);
            lstm_epilogue(smem, m0, n0, g_c[1],
                          g_x1h[pn], g_x1l[pn], K1T, 512,
                          nullptr, nullptr, 0, 0);
        }
        gridbar(++gen * GRIDC);

        // ---- fc: z_new = h1_new @ fcW^T + fcb -> x0[pn][0:256) and zs[t]
        if (cta < 64) {
            const int m0 = (cta & 15) * 64, n0 = (cta >> 4) * 64;
            if (tid < 64) ((float*)smem)[tid] = g_bfc[n0 + tid];
            gemm_main<64, 64>(smem, g_x1h[pn], g_x1l[pn], K1T, 512, m0,
                              g_Wfh, g_Wfl, KFT, n0, KFT);
            fc_epilogue64(smem, m0, n0,
                          g_x0h[pn], g_x0l[pn], K0T,
                          g_zsh + (size_t)t * Bsz * INsz,
                          g_zsl + (size_t)t * Bsz * INsz);
        }
        gridbar(++gen * GRIDC);
    }
}

// ---------------- final linear kernel ----------------
__global__ void __launch_bounds__(NTHR, 1)
lin_kernel(const bf16* __restrict__ Ah, const bf16* __restrict__ Al, int lda,
           const bf16* __restrict__ Wh, const bf16* __restrict__ Wl, int Ktot,
           const float* __restrict__ bias,
           float* __restrict__ fout, int ldo)
{
    extern __shared__ char smem[];
    const int tid = threadIdx.x;
    const int m0 = blockIdx.x * 128;
    const int n0 = blockIdx.y * 128;

    if (tid < 128) ((float*)smem)[tid] = bias[n0 + tid];

    gemm_main<128, 128>(smem, Ah, Al, lda, 0, m0, Wh, Wl, Ktot, n0, Ktot);

    const float* sbias = (const float*)smem;
    const float* smf = (const float*)(smem + 1024);

    #pragma unroll
    for (int it = 0; it < 8; it++) {
        const int idx = it * NTHR + tid;
        const int bl = idx >> 5;
        const int nq = (idx & 31) * 4;
        float4 v = *(const float4*)&smf[bl * SMF_STRIDE + nq];
        v.x += sbias[nq + 0]; v.y += sbias[nq + 1];
        v.z += sbias[nq + 2]; v.w += sbias[nq + 3];
        *(float4*)&fout[(size_t)(m0 + bl) * ldo + n0 + nq] = v;
    }
}

// ---------------- single fused prologue (packs + state init + barrier reset) ----------------
__global__ void prologue_kernel(
    const float* __restrict__ z0, const float* __restrict__ h0, const float* __restrict__ c0,
    const float* __restrict__ Wih0, const float* __restrict__ Whh0,
    const float* __restrict__ bih0, const float* __restrict__ bhh0,
    const float* __restrict__ Wih1, const float* __restrict__ Whh1,
    const float* __restrict__ bih1, const float* __restrict__ bhh1,
    const float* __restrict__ fcW, const float* __restrict__ fcb,
    const float* __restrict__ linW, const float* __restrict__ linb)
{
    const size_t stride = (size_t)gridDim.x * blockDim.x;
    const size_t t0 = (size_t)blockIdx.x * blockDim.x + threadIdx.x;

    if (t0 == 0) g_count = 0;   // reset grid barrier each launch/replay

    for (size_t idx = t0; idx < (size_t)2048 * K0T; idx += stride) {
        int rr = (int)(idx / K0T), k = (int)(idx - (size_t)rr * K0T);
        int h = rr >> 2, g = rr & 3;
        int orow = g * Hsz + h;
        float v = (k < INsz) ? Wih0[(size_t)orow * INsz + k]
                             : Whh0[(size_t)orow * Hsz + (k - INsz)];
        bf16 hi, lo; split_bf(v, hi, lo);
        g_W0h[idx] = hi; g_W0l[idx] = lo;
    }
    for (size_t idx = t0; idx < (size_t)2048 * K1T; idx += stride) {
        int rr = (int)(idx / K1T), k = (int)(idx - (size_t)rr * K1T);
        int h = rr >> 2, g = rr & 3;
        int orow = g * Hsz + h;
        float v = (k < Hsz) ? Wih1[(size_t)orow * Hsz + k]
                            : Whh1[(size_t)orow * Hsz + (k - Hsz)];
        bf16 hi, lo; split_bf(v, hi, lo);
        g_W1h[idx] = hi; g_W1l[idx] = lo;
    }
    for (size_t idx = t0; idx < (size_t)INsz * KFT; idx += stride) {
        bf16 hi, lo; split_bf(fcW[idx], hi, lo);
        g_Wfh[idx] = hi; g_Wfl[idx] = lo;
    }
    for (size_t idx = t0; idx < (size_t)OUTsz * KLT; idx += stride) {
        bf16 hi, lo; split_bf(linW[idx], hi, lo);
        g_Wlh[idx] = hi; g_Wll[idx] = lo;
    }
    for (size_t t = t0; t < 2048; t += stride) {
        int h = (int)(t >> 2), g = (int)(t & 3);
        int orow = g * Hsz + h;
        g_b0[t] = bih0[orow] + bhh0[orow];
        g_b1[t] = bih1[orow] + bhh1[orow];
    }
    for (size_t t = t0; t < INsz; t += stride) g_bfc[t] = fcb[t];
    for (size_t t = t0; t < OUTsz; t += stride) g_bln[t] = linb[t];
    const size_t BH = (size_t)Bsz * Hsz;
    for (size_t i = t0; i < BH; i += stride) {
        int b = (int)(i >> 9), h = (int)(i & 511);
        bf16 hi, lo;
        split_bf(h0[i], hi, lo);
        g_x0h[0][(size_t)b * K0T + 256 + h] = hi;
        g_x0l[0][(size_t)b * K0T + 256 + h] = lo;
        split_bf(h0[BH + i], hi, lo);
        g_x1h[0][(size_t)b * K1T + 512 + h] = hi;
        g_x1l[0][(size_t)b * K1T + 512 + h] = lo;
        g_c[0][i] = c0[i];
        g_c[1][i] = c0[BH + i];
    }
    for (size_t i = t0; i < (size_t)Bsz * INsz; i += stride) {
        int b = (int)(i >> 8), z = (int)(i & 255);
        bf16 hi, lo;
        split_bf(z0[i], hi, lo);
        g_x0h[0][(size_t)b * K0T + z] = hi;
        g_x0l[0][(size_t)b * K0T + z] = lo;
    }
}

// ---------------- host ----------------
extern "C" void kernel_launch(void* const* d_in, const int* in_sizes, int n_in,
                              void* d_out, int out_size)
{
    const float* z0   = (const float*)d_in[0];
    const float* h0   = (const float*)d_in[1];
    const float* c0   = (const float*)d_in[2];
    const float* Wih0 = (const float*)d_in[3];
    const float* Whh0 = (const float*)d_in[4];
    const float* bih0 = (const float*)d_in[5];
    const float* bhh0 = (const float*)d_in[6];
    const float* Wih1 = (const float*)d_in[7];
    const float* Whh1 = (const float*)d_in[8];
    const float* bih1 = (const float*)d_in[9];
    const float* bhh1 = (const float*)d_in[10];
    const float* fcW  = (const float*)d_in[11];
    const float* fcb  = (const float*)d_in[12];
    const float* linW = (const float*)d_in[13];
    const float* linb = (const float*)d_in[14];

    bf16 *zsh, *zsl, *Wlh, *Wll;
    float *bln;
    cudaGetSymbolAddress((void**)&zsh, g_zsh);
    cudaGetSymbolAddress((void**)&zsl, g_zsl);
    cudaGetSymbolAddress((void**)&Wlh, g_Wlh);
    cudaGetSymbolAddress((void**)&Wll, g_Wll);
    cudaGetSymbolAddress((void**)&bln, g_bln);

    cudaFuncSetAttribute(decoder_persistent,
                         cudaFuncAttributeMaxDynamicSharedMemorySize, SMEMSZ);
    cudaFuncSetAttribute(lin_kernel,
                         cudaFuncAttributeMaxDynamicSharedMemorySize, SMEMSZ);

    prologue_kernel<<<2048, 256>>>(z0, h0, c0, Wih0, Whh0, bih0, bhh0,
                                   Wih1, Whh1, bih1, bhh1, fcW, fcb, linW, linb);

    decoder_persistent<<<GRIDC, NTHR, SMEMSZ>>>();

    dim3 gfin((Tsz * Bsz) / 128, OUTsz / 128);  // (1024, 2)
    lin_kernel<<<gfin, NTHR, SMEMSZ>>>(
        zsh, zsl, INsz, Wlh, Wll, KLT, bln, (float*)d_out, OUTsz);
}

// round 11
// speedup vs baseline: 2.9234x; 1.0784x over previous
#include <cuda_runtime.h>
#include <cuda_bf16.h>
#include <math.h>
#include <stdint.h>

typedef __nv_bfloat16 bf16;

#define Bsz   1024
#define Hsz   512
#define INsz  256
#define OUTsz 256
#define Tsz   128
#define K0T   768
#define K1T   1024
#define KFT   512
#define KLT   256

#define LDSW  72                      // smem row stride (elems), 64 data + 8 pad
#define TILEB (128 * LDSW * 2)        // 18432 B per bf16 tile
#define SLOTB (4 * TILEB)             // 73728 B per pipeline stage (Ah,Al,Wh,Wl)
#define SMEMSZ (1024 + 3 * SLOTB)     // 222208 B (3-stage)
#define SMF_STRIDE 132                // fp32 staging row stride
#define NTHR 512
#define GRIDC 128

// ---------------- persistent device buffers ----------------
__device__ __align__(256) bf16  g_x0h[2][Bsz * K0T];
__device__ __align__(256) bf16  g_x0l[2][Bsz * K0T];
__device__ __align__(256) bf16  g_x1h[2][Bsz * K1T];
__device__ __align__(256) bf16  g_x1l[2][Bsz * K1T];
__device__ __align__(256) float g_c[2][Bsz * Hsz];
__device__ __align__(256) bf16  g_zsh[Tsz * Bsz * INsz];
__device__ __align__(256) bf16  g_zsl[Tsz * Bsz * INsz];
__device__ __align__(256) bf16  g_W0h[2048 * K0T];
__device__ __align__(256) bf16  g_W0l[2048 * K0T];
__device__ __align__(256) bf16  g_W1h[2048 * K1T];
__device__ __align__(256) bf16  g_W1l[2048 * K1T];
__device__ __align__(256) bf16  g_Wfh[INsz * KFT];
__device__ __align__(256) bf16  g_Wfl[INsz * KFT];
__device__ __align__(256) bf16  g_Wlh[OUTsz * KLT];
__device__ __align__(256) bf16  g_Wll[OUTsz * KLT];
__device__ __align__(256) float g_b0[2048];
__device__ __align__(256) float g_b1[2048];
__device__ __align__(256) float g_bfc[INsz];
__device__ __align__(256) float g_bln[OUTsz];
__device__ unsigned g_count;          // grid barrier counter (reset each launch)

// ---------------- helpers ----------------
__device__ __forceinline__ uint32_t smem_u32(const void* p) {
    uint32_t a;
    asm("{ .reg .u64 t; cvta.to.shared.u64 t, %1; cvt.u32.u64 %0, t; }" : "=r"(a) : "l"(p));
    return a;
}
__device__ __forceinline__ void cpa16(uint32_t s, const void* g) {
    asm volatile("cp.async.cg.shared.global [%0], [%1], 16;" :: "r"(s), "l"(g));
}
__device__ __forceinline__ void ldsm_x4(uint32_t* r, uint32_t a) {
    asm volatile("ldmatrix.sync.aligned.m8n8.x4.shared.b16 {%0,%1,%2,%3}, [%4];"
                 : "=r"(r[0]), "=r"(r[1]), "=r"(r[2]), "=r"(r[3]) : "r"(a));
}
__device__ __forceinline__ void ldsm_x2(uint32_t* r, uint32_t a) {
    asm volatile("ldmatrix.sync.aligned.m8n8.x2.shared.b16 {%0,%1}, [%2];"
                 : "=r"(r[0]), "=r"(r[1]) : "r"(a));
}
__device__ __forceinline__ void mma16816(float* c, const uint32_t* a, const uint32_t* b) {
    asm volatile(
        "mma.sync.aligned.m16n8k16.row.col.f32.bf16.bf16.f32 "
        "{%0,%1,%2,%3}, {%4,%5,%6,%7}, {%8,%9}, {%0,%1,%2,%3};"
        : "+f"(c[0]), "+f"(c[1]), "+f"(c[2]), "+f"(c[3])
        : "r"(a[0]), "r"(a[1]), "r"(a[2]), "r"(a[3]), "r"(b[0]), "r"(b[1]));
}
__device__ __forceinline__ float sigf(float x) { return 1.f / (1.f + expf(-x)); }
__device__ __forceinline__ void split_bf(float v, bf16& h, bf16& l) {
    h = __float2bfloat16(v);
    l = __float2bfloat16(v - __bfloat162float(h));
}
__device__ __forceinline__ uint32_t pk2(bf16 a, bf16 b) {
    return (uint32_t)__bfloat16_as_ushort(a) | ((uint32_t)__bfloat16_as_ushort(b) << 16);
}
template<int N>
__device__ __forceinline__ void zero_acc(float* a) {
    #pragma unroll
    for (int i = 0; i < N; i++) a[i] = 0.f;
}

// Software grid barrier. Cross-CTA data: writers use STG (reaches L2), readers
// use cp.async.cg (L2); __threadfence orders STG before the arrival.
__device__ __forceinline__ void gridbar(unsigned target) {
    __threadfence();
    __syncthreads();
    if (threadIdx.x == 0) {
        atomicAdd(&g_count, 1u);
        while (((volatile unsigned*)&g_count)[0] < target) __nanosleep(64);
    }
    __syncthreads();
}

// ---------------- 3-pass bf16 hi/lo GEMM, caller-owned acc ----------------
// acc layout: [MF][NF][4] flattened; MF=MTILE/64, NF=NTILE/32.
// 3-stage cp.async pipeline, single __syncthreads per chunk.
template<int MTILE, int NTILE>
__device__ __forceinline__ void gemm_k(
    char* smem, float* acc,
    const bf16* __restrict__ Ah, const bf16* __restrict__ Al, int lda, int aoff, int m0,
    const bf16* __restrict__ Wh, const bf16* __restrict__ Wl, int ldw, int n0,
    int kbeg, int kend)
{
    constexpr int MF = MTILE / 64;
    constexpr int NF = NTILE / 32;
    constexpr int WMR = MTILE / 4, WNR = NTILE / 4;

    const uint32_t sb = smem_u32(smem);
    const int tid = threadIdx.x;
    const int wid = tid >> 5, lane = tid & 31;
    const int wn = wid & 3, wm = wid >> 2;

    const uint32_t a_off = ((wm * WMR + (lane & 15)) * LDSW + (lane >> 4) * 8) * 2;
    uint32_t b_off;
    if constexpr (NF >= 2)
        b_off = ((wn * WNR + ((lane >> 4) << 3) + (lane & 7)) * LDSW
                 + ((lane >> 3) & 1) * 8) * 2;
    else
        b_off = ((wn * WNR + (lane & 7)) * LDSW + ((lane >> 3) & 1) * 8) * 2;

    const int lrow = tid >> 3;          // 0..63
    const int lk   = (tid & 7) * 8;     // elem offset
    const int nch  = (kend - kbeg) / 64;

    auto load_chunk = [&](int ch, int slot) {
        const uint32_t base = sb + 1024 + slot * SLOTB;
        const int k0 = kbeg + ch * 64;
        #pragma unroll
        for (int s = 0; s < MTILE / 64; s++) {
            const int r = lrow + s * 64;
            const uint32_t so = base + (r * LDSW + lk) * 2;
            const size_t ga = (size_t)(m0 + r) * lda + aoff + k0 + lk;
            cpa16(so,         Ah + ga);
            cpa16(so + TILEB, Al + ga);
        }
        if constexpr (NTILE >= 64) {
            #pragma unroll
            for (int s = 0; s < NTILE / 64; s++) {
                const int r = lrow + s * 64;
                const uint32_t so = base + 2 * TILEB + (r * LDSW + lk) * 2;
                const size_t gw = (size_t)(n0 + r) * ldw + k0 + lk;
                cpa16(so,         Wh + gw);
                cpa16(so + TILEB, Wl + gw);
            }
        } else {
            if (lrow < NTILE) {
                const uint32_t so = base + 2 * TILEB + (lrow * LDSW + lk) * 2;
                const size_t gw = (size_t)(n0 + lrow) * ldw + k0 + lk;
                cpa16(so,         Wh + gw);
                cpa16(so + TILEB, Wl + gw);
            }
        }
        asm volatile("cp.async.commit_group;");
    };

    load_chunk(0, 0);
    load_chunk(1, 1);

    for (int ch = 0; ch < nch; ch++) {
        if (ch + 1 < nch) asm volatile("cp.async.wait_group 1;");
        else              asm volatile("cp.async.wait_group 0;");
        __syncthreads();
        if (ch + 2 < nch) load_chunk(ch + 2, (ch + 2) % 3);

        const uint32_t base = sb + 1024 + (ch % 3) * SLOTB;
        const uint32_t abh = base + a_off;
        const uint32_t abl = base + TILEB + a_off;
        const uint32_t bbh = base + 2 * TILEB + b_off;
        const uint32_t bbl = base + 3 * TILEB + b_off;

        #pragma unroll
        for (int ks = 0; ks < 4; ks++) {
            uint32_t Ah4[MF][4], Al4[MF][4];
            #pragma unroll
            for (int mi = 0; mi < MF; mi++) {
                ldsm_x4(Ah4[mi], abh + mi * 16 * LDSW * 2 + ks * 32);
                ldsm_x4(Al4[mi], abl + mi * 16 * LDSW * 2 + ks * 32);
            }
            if constexpr (NF >= 2) {
                uint32_t Bh4[NF / 2][4], Bl4[NF / 2][4];
                #pragma unroll
                for (int n2 = 0; n2 < NF / 2; n2++) {
                    ldsm_x4(Bh4[n2], bbh + n2 * 16 * LDSW * 2 + ks * 32);
                    ldsm_x4(Bl4[n2], bbl + n2 * 16 * LDSW * 2 + ks * 32);
                }
                #pragma unroll
                for (int mi = 0; mi < MF; mi++)
                    #pragma unroll
                    for (int ni = 0; ni < NF; ni++)
                        mma16816(acc + (mi * NF + ni) * 4, Ah4[mi], &Bh4[ni >> 1][(ni & 1) * 2]);
                #pragma unroll
                for (int mi = 0; mi < MF; mi++)
                    #pragma unroll
                    for (int ni = 0; ni < NF; ni++)
                        mma16816(acc + (mi * NF + ni) * 4, Al4[mi], &Bh4[ni >> 1][(ni & 1) * 2]);
                #pragma unroll
                for (int mi = 0; mi < MF; mi++)
                    #pragma unroll
                    for (int ni = 0; ni < NF; ni++)
                        mma16816(acc + (mi * NF + ni) * 4, Ah4[mi], &Bl4[ni >> 1][(ni & 1) * 2]);
            } else {
                uint32_t Bh2[2], Bl2[2];
                ldsm_x2(Bh2, bbh + ks * 32);
                ldsm_x2(Bl2, bbl + ks * 32);
                #pragma unroll
                for (int mi = 0; mi < MF; mi++) {
                    mma16816(acc + mi * 4, Ah4[mi], Bh2);
                    mma16816(acc + mi * 4, Al4[mi], Bh2);
                    mma16816(acc + mi * 4, Ah4[mi], Bl2);
                }
            }
        }
    }
}

// Stage acc to fp32 smem (+1024, SMF_STRIDE floats/row). Leading sync protects
// the overlap with pipeline slot 0; trailing sync before epilogue reads.
template<int MTILE, int NTILE>
__device__ __forceinline__ void stage_acc(char* smem, const float* acc)
{
    __syncthreads();
    const int tid = threadIdx.x;
    const int wid = tid >> 5, lane = tid & 31;
    const int wn = wid & 3, wm = wid >> 2;
    constexpr int WMR = MTILE / 4, WNR = NTILE / 4;
    constexpr int MF = MTILE / 64, NF = NTILE / 32;
    float* smf = (float*)(smem + 1024);
    #pragma unroll
    for (int mi = 0; mi < MF; mi++) {
        const int m = wm * WMR + mi * 16 + (lane >> 2);
        #pragma unroll
        for (int ni = 0; ni < NF; ni++) {
            const int n = wn * WNR + ni * 8 + (lane & 3) * 2;
            const float* a = acc + (mi * NF + ni) * 4;
            *(float2*)&smf[m * SMF_STRIDE + n]       = make_float2(a[0], a[1]);
            *(float2*)&smf[(m + 8) * SMF_STRIDE + n] = make_float2(a[2], a[3]);
        }
    }
    __syncthreads();
}

// ---------------- LSTM epilogue (128x128 tile) ----------------
__device__ __forceinline__ void lstm_epilogue(
    char* smem, int m0, int n0, float* __restrict__ cst,
    bf16* __restrict__ d1h, bf16* __restrict__ d1l, int ld1, int off1,
    bf16* __restrict__ d2h, bf16* __restrict__ d2l, int ld2, int off2)
{
    const int tid = threadIdx.x;
    const float* sbias = (const float*)smem;
    const float* smf = (const float*)(smem + 1024);
    const int hb = n0 >> 2;

    #pragma unroll
    for (int it = 0; it < 8; it++) {
        const int idx = it * NTHR + tid;
        const int bl = idx >> 5, hl = idx & 31;
        float4 g = *(const float4*)&smf[bl * SMF_STRIDE + hl * 4];
        const float gi = g.x + sbias[hl * 4 + 0];
        const float gf = g.y + sbias[hl * 4 + 1];
        const float gg = g.z + sbias[hl * 4 + 2];
        const float go = g.w + sbias[hl * 4 + 3];
        const size_t ci = (size_t)(m0 + bl) * Hsz + hb + hl;
        const float cc = sigf(gf) * cst[ci] + sigf(gi) * tanhf(gg);
        cst[ci] = cc;
        const float hn = sigf(go) * tanhf(cc);
        bf16 hh, hlw; split_bf(hn, hh, hlw);
        const size_t o1 = (size_t)(m0 + bl) * ld1 + off1 + hb + hl;
        d1h[o1] = hh; d1l[o1] = hlw;
        if (d2h) {
            const size_t o2 = (size_t)(m0 + bl) * ld2 + off2 + hb + hl;
            d2h[o2] = hh; d2l[o2] = hlw;
        }
    }
    __syncthreads();
}

// ---------------- FC epilogue (64x32 tile, one float4 per thread) ----------------
__device__ __forceinline__ void fc_epilogue(
    char* smem, int m0, int n0,
    bf16* __restrict__ d1h, bf16* __restrict__ d1l, int ld1,
    bf16* __restrict__ zsh, bf16* __restrict__ zsl)
{
    const int tid = threadIdx.x;
    const float* sbias = (const float*)smem;
    const float* smf = (const float*)(smem + 1024);

    const int bl = tid >> 3;            // 0..63
    const int nq = (tid & 7) * 4;       // 0..28
    float4 v = *(const float4*)&smf[bl * SMF_STRIDE + nq];
    v.x += sbias[nq + 0]; v.y += sbias[nq + 1];
    v.z += sbias[nq + 2]; v.w += sbias[nq + 3];
    bf16 h0v, l0v, h1v, l1v, h2v, l2v, h3v, l3v;
    split_bf(v.x, h0v, l0v); split_bf(v.y, h1v, l1v);
    split_bf(v.z, h2v, l2v); split_bf(v.w, h3v, l3v);
    const uint2 vh = make_uint2(pk2(h0v, h1v), pk2(h2v, h3v));
    const uint2 vl = make_uint2(pk2(l0v, l1v), pk2(l2v, l3v));
    const size_t o1 = (size_t)(m0 + bl) * ld1 + n0 + nq;
    *(uint2*)(d1h + o1) = vh; *(uint2*)(d1l + o1) = vl;
    const size_t o2 = (size_t)(m0 + bl) * INsz + n0 + nq;
    *(uint2*)(zsh + o2) = vh; *(uint2*)(zsl + o2) = vl;
    __syncthreads();
}

// ---------------- persistent decoder ----------------
__global__ void __launch_bounds__(NTHR, 1) decoder_persistent()
{
    extern __shared__ char smem[];
    const int cta = blockIdx.x;
    const int tid = threadIdx.x;
    const int m0L = (cta & 7) * 128, n0L = (cta >> 3) * 128;
    const int m0F = (cta & 15) * 64, n0F = (cta >> 4) * 32;
    unsigned gen = 0;

    float acc[32];

    for (int t = 0; t < Tsz; t++) {
        const int p = t & 1, pn = p ^ 1;

        // ---- P1: L0 full (k 0..768) + epilogue
        if (tid < 128) ((float*)smem)[tid] = g_b0[n0L + tid];
        zero_acc<32>(acc);
        gemm_k<128, 128>(smem, acc, g_x0h[p], g_x0l[p], K0T, 0, m0L,
                         g_W0h, g_W0l, K0T, n0L, 0, K0T);
        stage_acc<128, 128>(smem, acc);
        lstm_epilogue(smem, m0L, n0L, g_c[0],
                      g_x1h[p], g_x1l[p], K1T, 0,
                      g_x0h[pn], g_x0l[pn], K0T, 256);
        gridbar(++gen * GRIDC);

        // ---- P2: L1 full (k 0..1024) + epilogue
        if (tid < 128) ((float*)smem)[tid] = g_b1[n0L + tid];
        zero_acc<32>(acc);
        gemm_k<128, 128>(smem, acc, g_x1h[p], g_x1l[p], K1T, 0, m0L,
                         g_W1h, g_W1l, K1T, n0L, 0, 1024);
        stage_acc<128, 128>(smem, acc);
        lstm_epilogue(smem, m0L, n0L, g_c[1],
                      g_x1h[pn], g_x1l[pn], K1T, 512,
                      nullptr, nullptr, 0, 0);
        gridbar(++gen * GRIDC);

        // ---- P3: fc (all 128 CTAs, 64x32 tiles)
        if (tid < 32) ((float*)smem)[tid] = g_bfc[n0F + tid];
        zero_acc<4>(acc);
        gemm_k<64, 32>(smem, acc, g_x1h[pn], g_x1l[pn], K1T, 512, m0F,
                       g_Wfh, g_Wfl, KFT, n0F, 0, 512);
        stage_acc<64, 32>(smem, acc);
        fc_epilogue(smem, m0F, n0F,
                    g_x0h[pn], g_x0l[pn], K0T,
                    g_zsh + (size_t)t * Bsz * INsz,
                    g_zsl + (size_t)t * Bsz * INsz);
        gridbar(++gen * GRIDC);
    }
}

// ---------------- final linear kernel ----------------
__global__ void __launch_bounds__(NTHR, 1)
lin_kernel(const bf16* __restrict__ Ah, const bf16* __restrict__ Al, int lda,
           const bf16* __restrict__ Wh, const bf16* __restrict__ Wl, int Ktot,
           const float* __restrict__ bias,
           float* __restrict__ fout, int ldo)
{
    extern __shared__ char smem[];
    const int tid = threadIdx.x;
    const int m0 = blockIdx.x * 128;
    const int n0 = blockIdx.y * 128;

    if (tid < 128) ((float*)smem)[tid] = bias[n0 + tid];

    float acc[32];
    zero_acc<32>(acc);
    gemm_k<128, 128>(smem, acc, Ah, Al, lda, 0, m0, Wh, Wl, Ktot, n0, 0, Ktot);
    stage_acc<128, 128>(smem, acc);

    const float* sbias = (const float*)smem;
    const float* smf = (const float*)(smem + 1024);

    #pragma unroll
    for (int it = 0; it < 8; it++) {
        const int idx = it * NTHR + tid;
        const int bl = idx >> 5;
        const int nq = (idx & 31) * 4;
        float4 v = *(const float4*)&smf[bl * SMF_STRIDE + nq];
        v.x += sbias[nq + 0]; v.y += sbias[nq + 1];
        v.z += sbias[nq + 2]; v.w += sbias[nq + 3];
        *(float4*)&fout[(size_t)(m0 + bl) * ldo + n0 + nq] = v;
    }
}

// ---------------- single fused prologue (packs + state init + barrier reset) ----------------
__global__ void prologue_kernel(
    const float* __restrict__ z0, const float* __restrict__ h0, const float* __restrict__ c0,
    const float* __restrict__ Wih0, const float* __restrict__ Whh0,
    const float* __restrict__ bih0, const float* __restrict__ bhh0,
    const float* __restrict__ Wih1, const float* __restrict__ Whh1,
    const float* __restrict__ bih1, const float* __restrict__ bhh1,
    const float* __restrict__ fcW, const float* __restrict__ fcb,
    const float* __restrict__ linW, const float* __restrict__ linb)
{
    const size_t stride = (size_t)gridDim.x * blockDim.x;
    const size_t t0 = (size_t)blockIdx.x * blockDim.x + threadIdx.x;

    if (t0 == 0) g_count = 0;   // reset grid barrier each launch/replay

    for (size_t idx = t0; idx < (size_t)2048 * K0T; idx += stride) {
        int rr = (int)(idx / K0T), k = (int)(idx - (size_t)rr * K0T);
        int h = rr >> 2, g = rr & 3;
        int orow = g * Hsz + h;
        float v = (k < INsz) ? Wih0[(size_t)orow * INsz + k]
                             : Whh0[(size_t)orow * Hsz + (k - INsz)];
        bf16 hi, lo; split_bf(v, hi, lo);
        g_W0h[idx] = hi; g_W0l[idx] = lo;
    }
    for (size_t idx = t0; idx < (size_t)2048 * K1T; idx += stride) {
        int rr = (int)(idx / K1T), k = (int)(idx - (size_t)rr * K1T);
        int h = rr >> 2, g = rr & 3;
        int orow = g * Hsz + h;
        float v = (k < Hsz) ? Wih1[(size_t)orow * Hsz + k]
                            : Whh1[(size_t)orow * Hsz + (k - Hsz)];
        bf16 hi, lo; split_bf(v, hi, lo);
        g_W1h[idx] = hi; g_W1l[idx] = lo;
    }
    for (size_t idx = t0; idx < (size_t)INsz * KFT; idx += stride) {
        bf16 hi, lo; split_bf(fcW[idx], hi, lo);
        g_Wfh[idx] = hi; g_Wfl[idx] = lo;
    }
    for (size_t idx = t0; idx < (size_t)OUTsz * KLT; idx += stride) {
        bf16 hi, lo; split_bf(linW[idx], hi, lo);
        g_Wlh[idx] = hi; g_Wll[idx] = lo;
    }
    for (size_t t = t0; t < 2048; t += stride) {
        int h = (int)(t >> 2), g = (int)(t & 3);
        int orow = g * Hsz + h;
        g_b0[t] = bih0[orow] + bhh0[orow];
        g_b1[t] = bih1[orow] + bhh1[orow];
    }
    for (size_t t = t0; t < INsz; t += stride) g_bfc[t] = fcb[t];
    for (size_t t = t0; t < OUTsz; t += stride) g_bln[t] = linb[t];
    const size_t BH = (size_t)Bsz * Hsz;
    for (size_t i = t0; i < BH; i += stride) {
        int b = (int)(i >> 9), h = (int)(i & 511);
        bf16 hi, lo;
        split_bf(h0[i], hi, lo);
        g_x0h[0][(size_t)b * K0T + 256 + h] = hi;
        g_x0l[0][(size_t)b * K0T + 256 + h] = lo;
        split_bf(h0[BH + i], hi, lo);
        g_x1h[0][(size_t)b * K1T + 512 + h] = hi;
        g_x1l[0][(size_t)b * K1T + 512 + h] = lo;
        g_c[0][i] = c0[i];
        g_c[1][i] = c0[BH + i];
    }
    for (size_t i = t0; i < (size_t)Bsz * INsz; i += stride) {
        int b = (int)(i >> 8), z = (int)(i & 255);
        bf16 hi, lo;
        split_bf(z0[i], hi, lo);
        g_x0h[0][(size_t)b * K0T + z] = hi;
        g_x0l[0][(size_t)b * K0T + z] = lo;
    }
}

// ---------------- host ----------------
extern "C" void kernel_launch(void* const* d_in, const int* in_sizes, int n_in,
                              void* d_out, int out_size)
{
    const float* z0   = (const float*)d_in[0];
    const float* h0   = (const float*)d_in[1];
    const float* c0   = (const float*)d_in[2];
    const float* Wih0 = (const float*)d_in[3];
    const float* Whh0 = (const float*)d_in[4];
    const float* bih0 = (const float*)d_in[5];
    const float* bhh0 = (const float*)d_in[6];
    const float* Wih1 = (const float*)d_in[7];
    const float* Whh1 = (const float*)d_in[8];
    const float* bih1 = (const float*)d_in[9];
    const float* bhh1 = (const float*)d_in[10];
    const float* fcW  = (const float*)d_in[11];
    const float* fcb  = (const float*)d_in[12];
    const float* linW = (const float*)d_in[13];
    const float* linb = (const float*)d_in[14];

    bf16 *zsh, *zsl, *Wlh, *Wll;
    float *bln;
    cudaGetSymbolAddress((void**)&zsh, g_zsh);
    cudaGetSymbolAddress((void**)&zsl, g_zsl);
    cudaGetSymbolAddress((void**)&Wlh, g_Wlh);
    cudaGetSymbolAddress((void**)&Wll, g_Wll);
    cudaGetSymbolAddress((void**)&bln, g_bln);

    cudaFuncSetAttribute(decoder_persistent,
                         cudaFuncAttributeMaxDynamicSharedMemorySize, SMEMSZ);
    cudaFuncSetAttribute(lin_kernel,
                         cudaFuncAttributeMaxDynamicSharedMemorySize, SMEMSZ);

    prologue_kernel<<<2048, 256>>>(z0, h0, c0, Wih0, Whh0, bih0, bhh0,
                                   Wih1, Whh1, bih1, bhh1, fcW, fcb, linW, linb);

    decoder_persistent<<<GRIDC, NTHR, SMEMSZ>>>();

    dim3 gfin((Tsz * Bsz) / 128, OUTsz / 128);  // (1024, 2)
    lin_kernel<<<gfin, NTHR, SMEMSZ>>>(
        zsh, zsl, INsz, Wlh, Wll, KLT, bln, (float*)d_out, OUTsz);
}

// round 12
// speedup vs baseline: 3.9360x; 1.3464x over previous
#include <cuda_runtime.h>
#include <cuda_fp16.h>
#include <math.h>
#include <stdint.h>

typedef __half fp16;

#define Bsz   1024
#define Hsz   512
#define INsz  256
#define OUTsz 256
#define Tsz   128
#define K0T   768
#define K1T   1024
#define KFT   512
#define KLT   256

#define LDSW  72                      // smem row stride (elems), 64 data + 8 pad
#define TILEB (128 * LDSW * 2)        // 18432 B per fp16 tile
#define SLOTB (3 * TILEB)             // 55296 B per pipeline stage (Ah,Al,W)
#define SMEMSZ (1024 + 3 * SLOTB)     // 166912 B (3-stage)
#define SMF_STRIDE 132                // fp32 staging row stride
#define NTHR 512
#define GRIDC 128

// ---------------- persistent device buffers ----------------
__device__ __align__(256) fp16  g_x0h[2][Bsz * K0T];
__device__ __align__(256) fp16  g_x0l[2][Bsz * K0T];
__device__ __align__(256) fp16  g_x1h[2][Bsz * K1T];
__device__ __align__(256) fp16  g_x1l[2][Bsz * K1T];
__device__ __align__(256) float g_c[2][Bsz * Hsz];
__device__ __align__(256) fp16  g_zsh[Tsz * Bsz * INsz];
__device__ __align__(256) fp16  g_zsl[Tsz * Bsz * INsz];
__device__ __align__(256) fp16  g_W0[2048 * K0T];
__device__ __align__(256) fp16  g_W1[2048 * K1T];
__device__ __align__(256) fp16  g_Wf[INsz * KFT];
__device__ __align__(256) fp16  g_Wl[OUTsz * KLT];
__device__ __align__(256) float g_b0[2048];
__device__ __align__(256) float g_b1[2048];
__device__ __align__(256) float g_bfc[INsz];
__device__ __align__(256) float g_bln[OUTsz];
__device__ unsigned g_count;          // grid barrier counter (reset each launch)

// ---------------- helpers ----------------
__device__ __forceinline__ uint32_t smem_u32(const void* p) {
    uint32_t a;
    asm("{ .reg .u64 t; cvta.to.shared.u64 t, %1; cvt.u32.u64 %0, t; }" : "=r"(a) : "l"(p));
    return a;
}
__device__ __forceinline__ void cpa16(uint32_t s, const void* g) {
    asm volatile("cp.async.cg.shared.global [%0], [%1], 16;" :: "r"(s), "l"(g));
}
__device__ __forceinline__ void ldsm_x4(uint32_t* r, uint32_t a) {
    asm volatile("ldmatrix.sync.aligned.m8n8.x4.shared.b16 {%0,%1,%2,%3}, [%4];"
                 : "=r"(r[0]), "=r"(r[1]), "=r"(r[2]), "=r"(r[3]) : "r"(a));
}
__device__ __forceinline__ void ldsm_x2(uint32_t* r, uint32_t a) {
    asm volatile("ldmatrix.sync.aligned.m8n8.x2.shared.b16 {%0,%1}, [%2];"
                 : "=r"(r[0]), "=r"(r[1]) : "r"(a));
}
__device__ __forceinline__ void mma16816(float* c, const uint32_t* a, const uint32_t* b) {
    asm volatile(
        "mma.sync.aligned.m16n8k16.row.col.f32.f16.f16.f32 "
        "{%0,%1,%2,%3}, {%4,%5,%6,%7}, {%8,%9}, {%0,%1,%2,%3};"
        : "+f"(c[0]), "+f"(c[1]), "+f"(c[2]), "+f"(c[3])
        : "r"(a[0]), "r"(a[1]), "r"(a[2]), "r"(a[3]), "r"(b[0]), "r"(b[1]));
}
__device__ __forceinline__ float sigf(float x) { return 1.f / (1.f + expf(-x)); }
__device__ __forceinline__ void split_h(float v, fp16& h, fp16& l) {
    h = __float2half(v);
    l = __float2half(v - __half2float(h));
}
__device__ __forceinline__ uint32_t pk2(fp16 a, fp16 b) {
    return (uint32_t)__half_as_ushort(a) | ((uint32_t)__half_as_ushort(b) << 16);
}
template<int N>
__device__ __forceinline__ void zero_acc(float* a) {
    #pragma unroll
    for (int i = 0; i < N; i++) a[i] = 0.f;
}

// Software grid barrier. Cross-CTA data: writers use STG (reaches L2), readers
// use cp.async.cg (L2); __threadfence orders STG before the arrival.
__device__ __forceinline__ void gridbar(unsigned target) {
    __threadfence();
    __syncthreads();
    if (threadIdx.x == 0) {
        atomicAdd(&g_count, 1u);
        while (((volatile unsigned*)&g_count)[0] < target) __nanosleep(64);
    }
    __syncthreads();
}

// ---------------- 2-pass fp16 GEMM (A hi/lo, W single), caller-owned acc ----------------
// acc layout: [MF][NF][4] flattened; MF=MTILE/64, NF=NTILE/32.
// 3-stage cp.async pipeline, single __syncthreads per chunk.
template<int MTILE, int NTILE>
__device__ __forceinline__ void gemm_k(
    char* smem, float* acc,
    const fp16* __restrict__ Ah, const fp16* __restrict__ Al, int lda, int aoff, int m0,
    const fp16* __restrict__ W, int ldw, int n0,
    int kbeg, int kend)
{
    constexpr int MF = MTILE / 64;
    constexpr int NF = NTILE / 32;
    constexpr int WMR = MTILE / 4, WNR = NTILE / 4;

    const uint32_t sb = smem_u32(smem);
    const int tid = threadIdx.x;
    const int wid = tid >> 5, lane = tid & 31;
    const int wn = wid & 3, wm = wid >> 2;

    const uint32_t a_off = ((wm * WMR + (lane & 15)) * LDSW + (lane >> 4) * 8) * 2;
    uint32_t b_off;
    if constexpr (NF >= 2)
        b_off = ((wn * WNR + ((lane >> 4) << 3) + (lane & 7)) * LDSW
                 + ((lane >> 3) & 1) * 8) * 2;
    else
        b_off = ((wn * WNR + (lane & 7)) * LDSW + ((lane >> 3) & 1) * 8) * 2;

    const int lrow = tid >> 3;          // 0..63
    const int lk   = (tid & 7) * 8;     // elem offset
    const int nch  = (kend - kbeg) / 64;

    auto load_chunk = [&](int ch, int slot) {
        const uint32_t base = sb + 1024 + slot * SLOTB;
        const int k0 = kbeg + ch * 64;
        #pragma unroll
        for (int s = 0; s < MTILE / 64; s++) {
            const int r = lrow + s * 64;
            const uint32_t so = base + (r * LDSW + lk) * 2;
            const size_t ga = (size_t)(m0 + r) * lda + aoff + k0 + lk;
            cpa16(so,         Ah + ga);
            cpa16(so + TILEB, Al + ga);
        }
        if constexpr (NTILE >= 64) {
            #pragma unroll
            for (int s = 0; s < NTILE / 64; s++) {
                const int r = lrow + s * 64;
                const uint32_t so = base + 2 * TILEB + (r * LDSW + lk) * 2;
                cpa16(so, W + (size_t)(n0 + r) * ldw + k0 + lk);
            }
        } else {
            if (lrow < NTILE) {
                const uint32_t so = base + 2 * TILEB + (lrow * LDSW + lk) * 2;
                cpa16(so, W + (size_t)(n0 + lrow) * ldw + k0 + lk);
            }
        }
        asm volatile("cp.async.commit_group;");
    };

    load_chunk(0, 0);
    load_chunk(1, 1);

    for (int ch = 0; ch < nch; ch++) {
        if (ch + 1 < nch) asm volatile("cp.async.wait_group 1;");
        else              asm volatile("cp.async.wait_group 0;");
        __syncthreads();
        if (ch + 2 < nch) load_chunk(ch + 2, (ch + 2) % 3);

        const uint32_t base = sb + 1024 + (ch % 3) * SLOTB;
        const uint32_t abh = base + a_off;
        const uint32_t abl = base + TILEB + a_off;
        const uint32_t bbw = base + 2 * TILEB + b_off;

        #pragma unroll
        for (int ks = 0; ks < 4; ks++) {
            uint32_t Ah4[MF][4], Al4[MF][4];
            #pragma unroll
            for (int mi = 0; mi < MF; mi++) {
                ldsm_x4(Ah4[mi], abh + mi * 16 * LDSW * 2 + ks * 32);
                ldsm_x4(Al4[mi], abl + mi * 16 * LDSW * 2 + ks * 32);
            }
            if constexpr (NF >= 2) {
                uint32_t W4[NF / 2][4];
                #pragma unroll
                for (int n2 = 0; n2 < NF / 2; n2++)
                    ldsm_x4(W4[n2], bbw + n2 * 16 * LDSW * 2 + ks * 32);
                #pragma unroll
                for (int mi = 0; mi < MF; mi++)
                    #pragma unroll
                    for (int ni = 0; ni < NF; ni++)
                        mma16816(acc + (mi * NF + ni) * 4, Ah4[mi], &W4[ni >> 1][(ni & 1) * 2]);
                #pragma unroll
                for (int mi = 0; mi < MF; mi++)
                    #pragma unroll
                    for (int ni = 0; ni < NF; ni++)
                        mma16816(acc + (mi * NF + ni) * 4, Al4[mi], &W4[ni >> 1][(ni & 1) * 2]);
            } else {
                uint32_t W2[2];
                ldsm_x2(W2, bbw + ks * 32);
                #pragma unroll
                for (int mi = 0; mi < MF; mi++) {
                    mma16816(acc + mi * 4, Ah4[mi], W2);
                    mma16816(acc + mi * 4, Al4[mi], W2);
                }
            }
        }
    }
}

// Stage acc to fp32 smem (+1024, SMF_STRIDE floats/row).
template<int MTILE, int NTILE>
__device__ __forceinline__ void stage_acc(char* smem, const float* acc)
{
    __syncthreads();
    const int tid = threadIdx.x;
    const int wid = tid >> 5, lane = tid & 31;
    const int wn = wid & 3, wm = wid >> 2;
    constexpr int WMR = MTILE / 4, WNR = NTILE / 4;
    constexpr int MF = MTILE / 64, NF = NTILE / 32;
    float* smf = (float*)(smem + 1024);
    #pragma unroll
    for (int mi = 0; mi < MF; mi++) {
        const int m = wm * WMR + mi * 16 + (lane >> 2);
        #pragma unroll
        for (int ni = 0; ni < NF; ni++) {
            const int n = wn * WNR + ni * 8 + (lane & 3) * 2;
            const float* a = acc + (mi * NF + ni) * 4;
            *(float2*)&smf[m * SMF_STRIDE + n]       = make_float2(a[0], a[1]);
            *(float2*)&smf[(m + 8) * SMF_STRIDE + n] = make_float2(a[2], a[3]);
        }
    }
    __syncthreads();
}

// ---------------- LSTM epilogue (128x128 tile) ----------------
__device__ __forceinline__ void lstm_epilogue(
    char* smem, int m0, int n0, float* __restrict__ cst,
    fp16* __restrict__ d1h, fp16* __restrict__ d1l, int ld1, int off1,
    fp16* __restrict__ d2h, fp16* __restrict__ d2l, int ld2, int off2)
{
    const int tid = threadIdx.x;
    const float* sbias = (const float*)smem;
    const float* smf = (const float*)(smem + 1024);
    const int hb = n0 >> 2;

    #pragma unroll
    for (int it = 0; it < 8; it++) {
        const int idx = it * NTHR + tid;
        const int bl = idx >> 5, hl = idx & 31;
        float4 g = *(const float4*)&smf[bl * SMF_STRIDE + hl * 4];
        const float gi = g.x + sbias[hl * 4 + 0];
        const float gf = g.y + sbias[hl * 4 + 1];
        const float gg = g.z + sbias[hl * 4 + 2];
        const float go = g.w + sbias[hl * 4 + 3];
        const size_t ci = (size_t)(m0 + bl) * Hsz + hb + hl;
        const float cc = sigf(gf) * cst[ci] + sigf(gi) * tanhf(gg);
        cst[ci] = cc;
        const float hn = sigf(go) * tanhf(cc);
        fp16 hh, hlw; split_h(hn, hh, hlw);
        const size_t o1 = (size_t)(m0 + bl) * ld1 + off1 + hb + hl;
        d1h[o1] = hh; d1l[o1] = hlw;
        if (d2h) {
            const size_t o2 = (size_t)(m0 + bl) * ld2 + off2 + hb + hl;
            d2h[o2] = hh; d2l[o2] = hlw;
        }
    }
    __syncthreads();
}

// ---------------- FC epilogue (64x32 tile, one float4 per thread) ----------------
__device__ __forceinline__ void fc_epilogue(
    char* smem, int m0, int n0,
    fp16* __restrict__ d1h, fp16* __restrict__ d1l, int ld1,
    fp16* __restrict__ zsh, fp16* __restrict__ zsl)
{
    const int tid = threadIdx.x;
    const float* sbias = (const float*)smem;
    const float* smf = (const float*)(smem + 1024);

    const int bl = tid >> 3;            // 0..63
    const int nq = (tid & 7) * 4;       // 0..28
    float4 v = *(const float4*)&smf[bl * SMF_STRIDE + nq];
    v.x += sbias[nq + 0]; v.y += sbias[nq + 1];
    v.z += sbias[nq + 2]; v.w += sbias[nq + 3];
    fp16 h0v, l0v, h1v, l1v, h2v, l2v, h3v, l3v;
    split_h(v.x, h0v, l0v); split_h(v.y, h1v, l1v);
    split_h(v.z, h2v, l2v); split_h(v.w, h3v, l3v);
    const uint2 vh = make_uint2(pk2(h0v, h1v), pk2(h2v, h3v));
    const uint2 vl = make_uint2(pk2(l0v, l1v), pk2(l2v, l3v));
    const size_t o1 = (size_t)(m0 + bl) * ld1 + n0 + nq;
    *(uint2*)(d1h + o1) = vh; *(uint2*)(d1l + o1) = vl;
    const size_t o2 = (size_t)(m0 + bl) * INsz + n0 + nq;
    *(uint2*)(zsh + o2) = vh; *(uint2*)(zsl + o2) = vl;
    __syncthreads();
}

// ---------------- persistent decoder ----------------
__global__ void __launch_bounds__(NTHR, 1) decoder_persistent()
{
    extern __shared__ char smem[];
    const int cta = blockIdx.x;
    const int tid = threadIdx.x;
    const int m0L = (cta & 7) * 128, n0L = (cta >> 3) * 128;
    const int m0F = (cta & 15) * 64, n0F = (cta >> 4) * 32;
    unsigned gen = 0;

    float acc[32];

    for (int t = 0; t < Tsz; t++) {
        const int p = t & 1, pn = p ^ 1;

        // ---- P1: L0 full (k 0..768) + epilogue
        if (tid < 128) ((float*)smem)[tid] = g_b0[n0L + tid];
        zero_acc<32>(acc);
        gemm_k<128, 128>(smem, acc, g_x0h[p], g_x0l[p], K0T, 0, m0L,
                         g_W0, K0T, n0L, 0, K0T);
        stage_acc<128, 128>(smem, acc);
        lstm_epilogue(smem, m0L, n0L, g_c[0],
                      g_x1h[p], g_x1l[p], K1T, 0,
                      g_x0h[pn], g_x0l[pn], K0T, 256);
        gridbar(++gen * GRIDC);

        // ---- P2: L1 full (k 0..1024) + epilogue
        if (tid < 128) ((float*)smem)[tid] = g_b1[n0L + tid];
        zero_acc<32>(acc);
        gemm_k<128, 128>(smem, acc, g_x1h[p], g_x1l[p], K1T, 0, m0L,
                         g_W1, K1T, n0L, 0, 1024);
        stage_acc<128, 128>(smem, acc);
        lstm_epilogue(smem, m0L, n0L, g_c[1],
                      g_x1h[pn], g_x1l[pn], K1T, 512,
                      nullptr, nullptr, 0, 0);
        gridbar(++gen * GRIDC);

        // ---- P3: fc (all 128 CTAs, 64x32 tiles)
        if (tid < 32) ((float*)smem)[tid] = g_bfc[n0F + tid];
        zero_acc<4>(acc);
        gemm_k<64, 32>(smem, acc, g_x1h[pn], g_x1l[pn], K1T, 512, m0F,
                       g_Wf, KFT, n0F, 0, 512);
        stage_acc<64, 32>(smem, acc);
        fc_epilogue(smem, m0F, n0F,
                    g_x0h[pn], g_x0l[pn], K0T,
                    g_zsh + (size_t)t * Bsz * INsz,
                    g_zsl + (size_t)t * Bsz * INsz);
        gridbar(++gen * GRIDC);
    }
}

// ---------------- final linear kernel ----------------
__global__ void __launch_bounds__(NTHR, 1)
lin_kernel(const fp16* __restrict__ Ah, const fp16* __restrict__ Al, int lda,
           const fp16* __restrict__ W, int Ktot,
           const float* __restrict__ bias,
           float* __restrict__ fout, int ldo)
{
    extern __shared__ char smem[];
    const int tid = threadIdx.x;
    const int m0 = blockIdx.x * 128;
    const int n0 = blockIdx.y * 128;

    if (tid < 128) ((float*)smem)[tid] = bias[n0 + tid];

    float acc[32];
    zero_acc<32>(acc);
    gemm_k<128, 128>(smem, acc, Ah, Al, lda, 0, m0, W, Ktot, n0, 0, Ktot);
    stage_acc<128, 128>(smem, acc);

    const float* sbias = (const float*)smem;
    const float* smf = (const float*)(smem + 1024);

    #pragma unroll
    for (int it = 0; it < 8; it++) {
        const int idx = it * NTHR + tid;
        const int bl = idx >> 5;
        const int nq = (idx & 31) * 4;
        float4 v = *(const float4*)&smf[bl * SMF_STRIDE + nq];
        v.x += sbias[nq + 0]; v.y += sbias[nq + 1];
        v.z += sbias[nq + 2]; v.w += sbias[nq + 3];
        *(float4*)&fout[(size_t)(m0 + bl) * ldo + n0 + nq] = v;
    }
}

// ---------------- single fused prologue (packs + state init + barrier reset) ----------------
__global__ void prologue_kernel(
    const float* __restrict__ z0, const float* __restrict__ h0, const float* __restrict__ c0,
    const float* __restrict__ Wih0, const float* __restrict__ Whh0,
    const float* __restrict__ bih0, const float* __restrict__ bhh0,
    const float* __restrict__ Wih1, const float* __restrict__ Whh1,
    const float* __restrict__ bih1, const float* __restrict__ bhh1,
    const float* __restrict__ fcW, const float* __restrict__ fcb,
    const float* __restrict__ linW, const float* __restrict__ linb)
{
    const size_t stride = (size_t)gridDim.x * blockDim.x;
    const size_t t0 = (size_t)blockIdx.x * blockDim.x + threadIdx.x;

    if (t0 == 0) g_count = 0;   // reset grid barrier each launch/replay

    for (size_t idx = t0; idx < (size_t)2048 * K0T; idx += stride) {
        int rr = (int)(idx / K0T), k = (int)(idx - (size_t)rr * K0T);
        int h = rr >> 2, g = rr & 3;
        int orow = g * Hsz + h;
        float v = (k < INsz) ? Wih0[(size_t)orow * INsz + k]
                             : Whh0[(size_t)orow * Hsz + (k - INsz)];
        g_W0[idx] = __float2half(v);
    }
    for (size_t idx = t0; idx < (size_t)2048 * K1T; idx += stride) {
        int rr = (int)(idx / K1T), k = (int)(idx - (size_t)rr * K1T);
        int h = rr >> 2, g = rr & 3;
        int orow = g * Hsz + h;
        float v = (k < Hsz) ? Wih1[(size_t)orow * Hsz + k]
                            : Whh1[(size_t)orow * Hsz + (k - Hsz)];
        g_W1[idx] = __float2half(v);
    }
    for (size_t idx = t0; idx < (size_t)INsz * KFT; idx += stride)
        g_Wf[idx] = __float2half(fcW[idx]);
    for (size_t idx = t0; idx < (size_t)OUTsz * KLT; idx += stride)
        g_Wl[idx] = __float2half(linW[idx]);
    for (size_t t = t0; t < 2048; t += stride) {
        int h = (int)(t >> 2), g = (int)(t & 3);
        int orow = g * Hsz + h;
        g_b0[t] = bih0[orow] + bhh0[orow];
        g_b1[t] = bih1[orow] + bhh1[orow];
    }
    for (size_t t = t0; t < INsz; t += stride) g_bfc[t] = fcb[t];
    for (size_t t = t0; t < OUTsz; t += stride) g_bln[t] = linb[t];
    const size_t BH = (size_t)Bsz * Hsz;
    for (size_t i = t0; i < BH; i += stride) {
        int b = (int)(i >> 9), h = (int)(i & 511);
        fp16 hi, lo;
        split_h(h0[i], hi, lo);
        g_x0h[0][(size_t)b * K0T + 256 + h] = hi;
        g_x0l[0][(size_t)b * K0T + 256 + h] = lo;
        split_h(h0[BH + i], hi, lo);
        g_x1h[0][(size_t)b * K1T + 512 + h] = hi;
        g_x1l[0][(size_t)b * K1T + 512 + h] = lo;
        g_c[0][i] = c0[i];
        g_c[1][i] = c0[BH + i];
    }
    for (size_t i = t0; i < (size_t)Bsz * INsz; i += stride) {
        int b = (int)(i >> 8), z = (int)(i & 255);
        fp16 hi, lo;
        split_h(z0[i], hi, lo);
        g_x0h[0][(size_t)b * K0T + z] = hi;
        g_x0l[0][(size_t)b * K0T + z] = lo;
    }
}

// ---------------- host ----------------
extern "C" void kernel_launch(void* const* d_in, const int* in_sizes, int n_in,
                              void* d_out, int out_size)
{
    const float* z0   = (const float*)d_in[0];
    const float* h0   = (const float*)d_in[1];
    const float* c0   = (const float*)d_in[2];
    const float* Wih0 = (const float*)d_in[3];
    const float* Whh0 = (const float*)d_in[4];
    const float* bih0 = (const float*)d_in[5];
    const float* bhh0 = (const float*)d_in[6];
    const float* Wih1 = (const float*)d_in[7];
    const float* Whh1 = (const float*)d_in[8];
    const float* bih1 = (const float*)d_in[9];
    const float* bhh1 = (const float*)d_in[10];
    const float* fcW  = (const float*)d_in[11];
    const float* fcb  = (const float*)d_in[12];
    const float* linW = (const float*)d_in[13];
    const float* linb = (const float*)d_in[14];

    fp16 *zsh, *zsl, *Wl;
    float *bln;
    cudaGetSymbolAddress((void**)&zsh, g_zsh);
    cudaGetSymbolAddress((void**)&zsl, g_zsl);
    cudaGetSymbolAddress((void**)&Wl,  g_Wl);
    cudaGetSymbolAddress((void**)&bln, g_bln);

    cudaFuncSetAttribute(decoder_persistent,
                         cudaFuncAttributeMaxDynamicSharedMemorySize, SMEMSZ);
    cudaFuncSetAttribute(lin_kernel,
                         cudaFuncAttributeMaxDynamicSharedMemorySize, SMEMSZ);

    prologue_kernel<<<2048, 256>>>(z0, h0, c0, Wih0, Whh0, bih0, bhh0,
                                   Wih1, Whh1, bih1, bhh1, fcW, fcb, linW, linb);

    decoder_persistent<<<GRIDC, NTHR, SMEMSZ>>>();

    dim3 gfin((Tsz * Bsz) / 128, OUTsz / 128);  // (1024, 2)
    lin_kernel<<<gfin, NTHR, SMEMSZ>>>(
        zsh, zsl, INsz, Wl, KLT, bln, (float*)d_out, OUTsz);
}

// round 13
// speedup vs baseline: 6.4733x; 1.6447x over previous
#include <cuda_runtime.h>
#include <cuda_fp16.h>
#include <math.h>
#include <stdint.h>

typedef __half fp16;

#define Bsz   1024
#define Hsz   512
#define INsz  256
#define OUTsz 256
#define Tsz   128
#define K0T   768
#define K1T   1024
#define KFT   512
#define KLT   256

#define LDSW  72                      // smem row stride (elems), 64 data + 8 pad
#define TILEB (128 * LDSW * 2)        // 18432 B per fp16 tile
#define SLOTB (2 * TILEB)             // 36864 B per pipeline stage (A, W)
#define SMEMSZ (1024 + 3 * SLOTB)     // 111616 B (3-stage)
#define SMF_STRIDE 132                // fp32 staging row stride
#define NTHR 512
#define GRIDC 128

// ---------------- persistent device buffers ----------------
__device__ __align__(256) fp16  g_x0[2][Bsz * K0T];
__device__ __align__(256) fp16  g_x1[2][Bsz * K1T];
__device__ __align__(256) float g_c[2][Bsz * Hsz];
__device__ __align__(256) fp16  g_zs[Tsz * Bsz * INsz];
__device__ __align__(256) fp16  g_W0[2048 * K0T];
__device__ __align__(256) fp16  g_W1[2048 * K1T];
__device__ __align__(256) fp16  g_Wf[INsz * KFT];
__device__ __align__(256) fp16  g_Wl[OUTsz * KLT];
__device__ __align__(256) float g_b0[2048];
__device__ __align__(256) float g_b1[2048];
__device__ __align__(256) float g_bfc[INsz];
__device__ __align__(256) float g_bln[OUTsz];
__device__ unsigned g_count;          // grid barrier counter (reset each launch)

// ---------------- helpers ----------------
__device__ __forceinline__ uint32_t smem_u32(const void* p) {
    uint32_t a;
    asm("{ .reg .u64 t; cvta.to.shared.u64 t, %1; cvt.u32.u64 %0, t; }" : "=r"(a) : "l"(p));
    return a;
}
__device__ __forceinline__ void cpa16(uint32_t s, const void* g) {
    asm volatile("cp.async.cg.shared.global [%0], [%1], 16;" :: "r"(s), "l"(g));
}
__device__ __forceinline__ void ldsm_x4(uint32_t* r, uint32_t a) {
    asm volatile("ldmatrix.sync.aligned.m8n8.x4.shared.b16 {%0,%1,%2,%3}, [%4];"
                 : "=r"(r[0]), "=r"(r[1]), "=r"(r[2]), "=r"(r[3]) : "r"(a));
}
__device__ __forceinline__ void ldsm_x2(uint32_t* r, uint32_t a) {
    asm volatile("ldmatrix.sync.aligned.m8n8.x2.shared.b16 {%0,%1}, [%2];"
                 : "=r"(r[0]), "=r"(r[1]) : "r"(a));
}
__device__ __forceinline__ void mma16816(float* c, const uint32_t* a, const uint32_t* b) {
    asm volatile(
        "mma.sync.aligned.m16n8k16.row.col.f32.f16.f16.f32 "
        "{%0,%1,%2,%3}, {%4,%5,%6,%7}, {%8,%9}, {%0,%1,%2,%3};"
        : "+f"(c[0]), "+f"(c[1]), "+f"(c[2]), "+f"(c[3])
        : "r"(a[0]), "r"(a[1]), "r"(a[2]), "r"(a[3]), "r"(b[0]), "r"(b[1]));
}
__device__ __forceinline__ float sigf(float x) { return 1.f / (1.f + expf(-x)); }
__device__ __forceinline__ uint32_t pk2(fp16 a, fp16 b) {
    return (uint32_t)__half_as_ushort(a) | ((uint32_t)__half_as_ushort(b) << 16);
}
template<int N>
__device__ __forceinline__ void zero_acc(float* a) {
    #pragma unroll
    for (int i = 0; i < N; i++) a[i] = 0.f;
}

// Software grid barrier. Cross-CTA data: writers use STG (reaches L2), readers
// use cp.async.cg (L2); __threadfence orders STG before the arrival.
__device__ __forceinline__ void gridbar(unsigned target) {
    __threadfence();
    __syncthreads();
    if (threadIdx.x == 0) {
        atomicAdd(&g_count, 1u);
        while (((volatile unsigned*)&g_count)[0] < target) __nanosleep(64);
    }
    __syncthreads();
}

// ---------------- single-pass fp16 GEMM, caller-owned acc ----------------
// acc layout: [MF][NF][4] flattened; MF=MTILE/64, NF=NTILE/32.
// 3-stage cp.async pipeline, single __syncthreads per chunk.
template<int MTILE, int NTILE>
__device__ __forceinline__ void gemm_k(
    char* smem, float* acc,
    const fp16* __restrict__ A, int lda, int aoff, int m0,
    const fp16* __restrict__ W, int ldw, int n0,
    int kbeg, int kend)
{
    constexpr int MF = MTILE / 64;
    constexpr int NF = NTILE / 32;
    constexpr int WMR = MTILE / 4, WNR = NTILE / 4;

    const uint32_t sb = smem_u32(smem);
    const int tid = threadIdx.x;
    const int wid = tid >> 5, lane = tid & 31;
    const int wn = wid & 3, wm = wid >> 2;

    const uint32_t a_off = ((wm * WMR + (lane & 15)) * LDSW + (lane >> 4) * 8) * 2;
    uint32_t b_off;
    if constexpr (NF >= 2)
        b_off = ((wn * WNR + ((lane >> 4) << 3) + (lane & 7)) * LDSW
                 + ((lane >> 3) & 1) * 8) * 2;
    else
        b_off = ((wn * WNR + (lane & 7)) * LDSW + ((lane >> 3) & 1) * 8) * 2;

    const int lrow = tid >> 3;          // 0..63
    const int lk   = (tid & 7) * 8;     // elem offset
    const int nch  = (kend - kbeg) / 64;

    auto load_chunk = [&](int ch, int slot) {
        const uint32_t base = sb + 1024 + slot * SLOTB;
        const int k0 = kbeg + ch * 64;
        #pragma unroll
        for (int s = 0; s < MTILE / 64; s++) {
            const int r = lrow + s * 64;
            const uint32_t so = base + (r * LDSW + lk) * 2;
            cpa16(so, A + (size_t)(m0 + r) * lda + aoff + k0 + lk);
        }
        if constexpr (NTILE >= 64) {
            #pragma unroll
            for (int s = 0; s < NTILE / 64; s++) {
                const int r = lrow + s * 64;
                const uint32_t so = base + TILEB + (r * LDSW + lk) * 2;
                cpa16(so, W + (size_t)(n0 + r) * ldw + k0 + lk);
            }
        } else {
            if (lrow < NTILE) {
                const uint32_t so = base + TILEB + (lrow * LDSW + lk) * 2;
                cpa16(so, W + (size_t)(n0 + lrow) * ldw + k0 + lk);
            }
        }
        asm volatile("cp.async.commit_group;");
    };

    load_chunk(0, 0);
    load_chunk(1, 1);

    for (int ch = 0; ch < nch; ch++) {
        if (ch + 1 < nch) asm volatile("cp.async.wait_group 1;");
        else              asm volatile("cp.async.wait_group 0;");
        __syncthreads();
        if (ch + 2 < nch) load_chunk(ch + 2, (ch + 2) % 3);

        const uint32_t base = sb + 1024 + (ch % 3) * SLOTB;
        const uint32_t aba = base + a_off;
        const uint32_t bbw = base + TILEB + b_off;

        #pragma unroll
        for (int ks = 0; ks < 4; ks++) {
            uint32_t A4[MF][4];
            #pragma unroll
            for (int mi = 0; mi < MF; mi++)
                ldsm_x4(A4[mi], aba + mi * 16 * LDSW * 2 + ks * 32);
            if constexpr (NF >= 2) {
                uint32_t W4[NF / 2][4];
                #pragma unroll
                for (int n2 = 0; n2 < NF / 2; n2++)
                    ldsm_x4(W4[n2], bbw + n2 * 16 * LDSW * 2 + ks * 32);
                #pragma unroll
                for (int mi = 0; mi < MF; mi++)
                    #pragma unroll
                    for (int ni = 0; ni < NF; ni++)
                        mma16816(acc + (mi * NF + ni) * 4, A4[mi], &W4[ni >> 1][(ni & 1) * 2]);
            } else {
                uint32_t W2[2];
                ldsm_x2(W2, bbw + ks * 32);
                #pragma unroll
                for (int mi = 0; mi < MF; mi++)
                    mma16816(acc + mi * 4, A4[mi], W2);
            }
        }
    }
}

// Stage acc to fp32 smem (+1024, SMF_STRIDE floats/row).
template<int MTILE, int NTILE>
__device__ __forceinline__ void stage_acc(char* smem, const float* acc)
{
    __syncthreads();
    const int tid = threadIdx.x;
    const int wid = tid >> 5, lane = tid & 31;
    const int wn = wid & 3, wm = wid >> 2;
    constexpr int WMR = MTILE / 4, WNR = NTILE / 4;
    constexpr int MF = MTILE / 64, NF = NTILE / 32;
    float* smf = (float*)(smem + 1024);
    #pragma unroll
    for (int mi = 0; mi < MF; mi++) {
        const int m = wm * WMR + mi * 16 + (lane >> 2);
        #pragma unroll
        for (int ni = 0; ni < NF; ni++) {
            const int n = wn * WNR + ni * 8 + (lane & 3) * 2;
            const float* a = acc + (mi * NF + ni) * 4;
            *(float2*)&smf[m * SMF_STRIDE + n]       = make_float2(a[0], a[1]);
            *(float2*)&smf[(m + 8) * SMF_STRIDE + n] = make_float2(a[2], a[3]);
        }
    }
    __syncthreads();
}

// ---------------- LSTM epilogue (128x128 tile) ----------------
__device__ __forceinline__ void lstm_epilogue(
    char* smem, int m0, int n0, float* __restrict__ cst,
    fp16* __restrict__ d1, int ld1, int off1,
    fp16* __restrict__ d2, int ld2, int off2)
{
    const int tid = threadIdx.x;
    const float* sbias = (const float*)smem;
    const float* smf = (const float*)(smem + 1024);
    const int hb = n0 >> 2;

    #pragma unroll
    for (int it = 0; it < 8; it++) {
        const int idx = it * NTHR + tid;
        const int bl = idx >> 5, hl = idx & 31;
        float4 g = *(const float4*)&smf[bl * SMF_STRIDE + hl * 4];
        const float gi = g.x + sbias[hl * 4 + 0];
        const float gf = g.y + sbias[hl * 4 + 1];
        const float gg = g.z + sbias[hl * 4 + 2];
        const float go = g.w + sbias[hl * 4 + 3];
        const size_t ci = (size_t)(m0 + bl) * Hsz + hb + hl;
        const float cc = sigf(gf) * cst[ci] + sigf(gi) * tanhf(gg);
        cst[ci] = cc;
        const fp16 hn = __float2half(sigf(go) * tanhf(cc));
        d1[(size_t)(m0 + bl) * ld1 + off1 + hb + hl] = hn;
        if (d2) d2[(size_t)(m0 + bl) * ld2 + off2 + hb + hl] = hn;
    }
    __syncthreads();
}

// ---------------- FC epilogue (64x32 tile, one float4 per thread) ----------------
__device__ __forceinline__ void fc_epilogue(
    char* smem, int m0, int n0,
    fp16* __restrict__ d1, int ld1,
    fp16* __restrict__ zs)
{
    const int tid = threadIdx.x;
    const float* sbias = (const float*)smem;
    const float* smf = (const float*)(smem + 1024);

    const int bl = tid >> 3;            // 0..63
    const int nq = (tid & 7) * 4;       // 0..28
    float4 v = *(const float4*)&smf[bl * SMF_STRIDE + nq];
    v.x += sbias[nq + 0]; v.y += sbias[nq + 1];
    v.z += sbias[nq + 2]; v.w += sbias[nq + 3];
    const uint2 vh = make_uint2(pk2(__float2half(v.x), __float2half(v.y)),
                                pk2(__float2half(v.z), __float2half(v.w)));
    *(uint2*)(d1 + (size_t)(m0 + bl) * ld1 + n0 + nq) = vh;
    *(uint2*)(zs + (size_t)(m0 + bl) * INsz + n0 + nq) = vh;
    __syncthreads();
}

// ---------------- persistent decoder ----------------
__global__ void __launch_bounds__(NTHR, 1) decoder_persistent()
{
    extern __shared__ char smem[];
    const int cta = blockIdx.x;
    const int tid = threadIdx.x;
    const int m0L = (cta & 7) * 128, n0L = (cta >> 3) * 128;
    const int m0F = (cta & 15) * 64, n0F = (cta >> 4) * 32;
    unsigned gen = 0;

    float acc[32];

    for (int t = 0; t < Tsz; t++) {
        const int p = t & 1, pn = p ^ 1;

        // ---- P1: L0 full (k 0..768) + epilogue
        if (tid < 128) ((float*)smem)[tid] = g_b0[n0L + tid];
        zero_acc<32>(acc);
        gemm_k<128, 128>(smem, acc, g_x0[p], K0T, 0, m0L,
                         g_W0, K0T, n0L, 0, K0T);
        stage_acc<128, 128>(smem, acc);
        lstm_epilogue(smem, m0L, n0L, g_c[0],
                      g_x1[p], K1T, 0,
                      g_x0[pn], K0T, 256);
        gridbar(++gen * GRIDC);

        // ---- P2: L1 full (k 0..1024) + epilogue
        if (tid < 128) ((float*)smem)[tid] = g_b1[n0L + tid];
        zero_acc<32>(acc);
        gemm_k<128, 128>(smem, acc, g_x1[p], K1T, 0, m0L,
                         g_W1, K1T, n0L, 0, 1024);
        stage_acc<128, 128>(smem, acc);
        lstm_epilogue(smem, m0L, n0L, g_c[1],
                      g_x1[pn], K1T, 512,
                      nullptr, 0, 0);
        gridbar(++gen * GRIDC);

        // ---- P3: fc (all 128 CTAs, 64x32 tiles)
        if (tid < 32) ((float*)smem)[tid] = g_bfc[n0F + tid];
        zero_acc<4>(acc);
        gemm_k<64, 32>(smem, acc, g_x1[pn], K1T, 512, m0F,
                       g_Wf, KFT, n0F, 0, 512);
        stage_acc<64, 32>(smem, acc);
        fc_epilogue(smem, m0F, n0F,
                    g_x0[pn], K0T,
                    g_zs + (size_t)t * Bsz * INsz);
        gridbar(++gen * GRIDC);
    }
}

// ---------------- final linear kernel ----------------
__global__ void __launch_bounds__(NTHR, 1)
lin_kernel(const fp16* __restrict__ A, int lda,
           const fp16* __restrict__ W, int Ktot,
           const float* __restrict__ bias,
           float* __restrict__ fout, int ldo)
{
    extern __shared__ char smem[];
    const int tid = threadIdx.x;
    const int m0 = blockIdx.x * 128;
    const int n0 = blockIdx.y * 128;

    if (tid < 128) ((float*)smem)[tid] = bias[n0 + tid];

    float acc[32];
    zero_acc<32>(acc);
    gemm_k<128, 128>(smem, acc, A, lda, 0, m0, W, Ktot, n0, 0, Ktot);
    stage_acc<128, 128>(smem, acc);

    const float* sbias = (const float*)smem;
    const float* smf = (const float*)(smem + 1024);

    #pragma unroll
    for (int it = 0; it < 8; it++) {
        const int idx = it * NTHR + tid;
        const int bl = idx >> 5;
        const int nq = (idx & 31) * 4;
        float4 v = *(const float4*)&smf[bl * SMF_STRIDE + nq];
        v.x += sbias[nq + 0]; v.y += sbias[nq + 1];
        v.z += sbias[nq + 2]; v.w += sbias[nq + 3];
        *(float4*)&fout[(size_t)(m0 + bl) * ldo + n0 + nq] = v;
    }
}

// ---------------- single fused prologue (packs + state init + barrier reset) ----------------
__global__ void prologue_kernel(
    const float* __restrict__ z0, const float* __restrict__ h0, const float* __restrict__ c0,
    const float* __restrict__ Wih0, const float* __restrict__ Whh0,
    const float* __restrict__ bih0, const float* __restrict__ bhh0,
    const float* __restrict__ Wih1, const float* __restrict__ Whh1,
    const float* __restrict__ bih1, const float* __restrict__ bhh1,
    const float* __restrict__ fcW, const float* __restrict__ fcb,
    const float* __restrict__ linW, const float* __restrict__ linb)
{
    const size_t stride = (size_t)gridDim.x * blockDim.x;
    const size_t t0 = (size_t)blockIdx.x * blockDim.x + threadIdx.x;

    if (t0 == 0) g_count = 0;   // reset grid barrier each launch/replay

    for (size_t idx = t0; idx < (size_t)2048 * K0T; idx += stride) {
        int rr = (int)(idx / K0T), k = (int)(idx - (size_t)rr * K0T);
        int h = rr >> 2, g = rr & 3;
        int orow = g * Hsz + h;
        float v = (k < INsz) ? Wih0[(size_t)orow * INsz + k]
                             : Whh0[(size_t)orow * Hsz + (k - INsz)];
        g_W0[idx] = __float2half(v);
    }
    for (size_t idx = t0; idx < (size_t)2048 * K1T; idx += stride) {
        int rr = (int)(idx / K1T), k = (int)(idx - (size_t)rr * K1T);
        int h = rr >> 2, g = rr & 3;
        int orow = g * Hsz + h;
        float v = (k < Hsz) ? Wih1[(size_t)orow * Hsz + k]
                            : Whh1[(size_t)orow * Hsz + (k - Hsz)];
        g_W1[idx] = __float2half(v);
    }
    for (size_t idx = t0; idx < (size_t)INsz * KFT; idx += stride)
        g_Wf[idx] = __float2half(fcW[idx]);
    for (size_t idx = t0; idx < (size_t)OUTsz * KLT; idx += stride)
        g_Wl[idx] = __float2half(linW[idx]);
    for (size_t t = t0; t < 2048; t += stride) {
        int h = (int)(t >> 2), g = (int)(t & 3);
        int orow = g * Hsz + h;
        g_b0[t] = bih0[orow] + bhh0[orow];
        g_b1[t] = bih1[orow] + bhh1[orow];
    }
    for (size_t t = t0; t < INsz; t += stride) g_bfc[t] = fcb[t];
    for (size_t t = t0; t < OUTsz; t += stride) g_bln[t] = linb[t];
    const size_t BH = (size_t)Bsz * Hsz;
    for (size_t i = t0; i < BH; i += stride) {
        int b = (int)(i >> 9), h = (int)(i & 511);
        g_x0[0][(size_t)b * K0T + 256 + h] = __float2half(h0[i]);
        g_x1[0][(size_t)b * K1T + 512 + h] = __float2half(h0[BH + i]);
        g_c[0][i] = c0[i];
        g_c[1][i] = c0[BH + i];
    }
    for (size_t i = t0; i < (size_t)Bsz * INsz; i += stride) {
        int b = (int)(i >> 8), z = (int)(i & 255);
        g_x0[0][(size_t)b * K0T + z] = __float2half(z0[i]);
    }
}

// ---------------- host ----------------
extern "C" void kernel_launch(void* const* d_in, const int* in_sizes, int n_in,
                              void* d_out, int out_size)
{
    const float* z0   = (const float*)d_in[0];
    const float* h0   = (const float*)d_in[1];
    const float* c0   = (const float*)d_in[2];
    const float* Wih0 = (const float*)d_in[3];
    const float* Whh0 = (const float*)d_in[4];
    const float* bih0 = (const float*)d_in[5];
    const float* bhh0 = (const float*)d_in[6];
    const float* Wih1 = (const float*)d_in[7];
    const float* Whh1 = (const float*)d_in[8];
    const float* bih1 = (const float*)d_in[9];
    const float* bhh1 = (const float*)d_in[10];
    const float* fcW  = (const float*)d_in[11];
    const float* fcb  = (const float*)d_in[12];
    const float* linW = (const float*)d_in[13];
    const float* linb = (const float*)d_in[14];

    fp16 *zs, *Wl;
    float *bln;
    cudaGetSymbolAddress((void**)&zs,  g_zs);
    cudaGetSymbolAddress((void**)&Wl,  g_Wl);
    cudaGetSymbolAddress((void**)&bln, g_bln);

    cudaFuncSetAttribute(decoder_persistent,
                         cudaFuncAttributeMaxDynamicSharedMemorySize, SMEMSZ);
    cudaFuncSetAttribute(lin_kernel,
                         cudaFuncAttributeMaxDynamicSharedMemorySize, SMEMSZ);

    prologue_kernel<<<2048, 256>>>(z0, h0, c0, Wih0, Whh0, bih0, bhh0,
                                   Wih1, Whh1, bih1, bhh1, fcW, fcb, linW, linb);

    decoder_persistent<<<GRIDC, NTHR, SMEMSZ>>>();

    dim3 gfin((Tsz * Bsz) / 128, OUTsz / 128);  // (1024, 2)
    lin_kernel<<<gfin, NTHR, SMEMSZ>>>(
        zs, INsz, Wl, KLT, bln, (float*)d_out, OUTsz);
}